// round 12
// baseline (speedup 1.0000x reference)
#include <cuda_runtime.h>
#include <cuda_fp16.h>
#include <mma.h>
#include <math.h>
#include <stdint.h>

using namespace nvcuda;
using fp16 = __half;

#define LATENT 256
#define HID    1024
#define NOUT   128
#define SEQL   96

#define NTHREADS 256
#define NBLOCKS  128
#define LDA    72
#define ABLK   9216          // elems per 128x72 block
#define ABLKB  18432         // bytes per 128x72 fp16 block
#define NSTAGE 6
#define STGMAX 36864         // bytes per stage buffer (A + B at NFW=4)

// smem: 1024 align slack + 1024 hdr (mbars) + 6 stage buffers = 223232
#define SMEM_BYTES (1024 + 1024 + NSTAGE * STGMAX)

// ---------------- device scratch (packed layouts) ----------------
__device__ __align__(16) fp16 g_lin1p[32 * 4 * 4608];     // BN=64, K=256
__device__ __align__(16) fp16 g_wih0p[32 * 2 * 9216];     // BN=128 gated, K=128
__device__ __align__(16) fp16 g_whh0p[32 * 16 * 9216];    // BN=128 gated, K=1024
__device__ __align__(16) fp16 g_wih1p[32 * 16 * 9216];
__device__ __align__(16) fp16 g_whh1p[32 * 16 * 9216];
__device__ __align__(16) fp16 g_p1p[32 * 16 * 2304];      // BN=32, K=1024
__device__ __align__(16) float4 g_p2q[256 * 128];         // p2_w transposed k-quad major
// activations: single fp16 plane, packed [kchunk][mgroup][128 x 72]
__device__ __align__(16) fp16 g_zp[4 * 4 * 9216];
__device__ __align__(16) fp16 g_xp[2 * 4 * 9216];
__device__ __align__(16) fp16 g_h1p[2][16 * 4 * 9216];    // [pingpong]
__device__ __align__(16) fp16 g_h2p[2][16 * 4 * 9216];
__device__ float g_c1[2][512 * HID];
__device__ float g_c2[2][512 * HID];
__device__ float g_u[512 * 2 * HID];
__device__ float g_t[512 * HID];
// barriers
__device__ volatile unsigned g_arrive[256];               // global (S0 only)
__device__ volatile unsigned g_release;
__device__ __align__(128) volatile unsigned g_flag[4][32]; // per-mg-group flags

typedef wmma::fragment<wmma::accumulator, 16, 16, 16, float> CFrag;
typedef wmma::fragment<wmma::matrix_a, 16, 16, 16, fp16, wmma::row_major> AFrag;
typedef wmma::fragment<wmma::matrix_b, 16, 16, 16, fp16, wmma::col_major> BFrag;

// ---------------- PTX helpers ----------------
__device__ __forceinline__ uint32_t smem_u32(const void* p) {
    uint32_t a;
    asm("{ .reg .u64 t; cvta.to.shared.u64 t, %1; cvt.u32.u64 %0, t; }" : "=r"(a) : "l"(p));
    return a;
}
#define MBAR_INIT(a, c) \
    asm volatile("mbarrier.init.shared.b64 [%0], %1;" :: "r"(a), "r"((uint32_t)(c)) : "memory")
#define MBAR_EXPECT(a, n) \
    asm volatile("mbarrier.arrive.expect_tx.shared.b64 _, [%0], %1;" :: "r"(a), "r"((uint32_t)(n)) : "memory")
#define MBAR_ARRIVE(a) \
    asm volatile("mbarrier.arrive.shared.b64 _, [%0];" :: "r"((uint32_t)(a)) : "memory")
#define MBAR_WAIT(a, par) do { \
    uint32_t _m = (a), _p = (par), _d; \
    asm volatile("{\n\t.reg .pred p;\n\t" \
        "mbarrier.try_wait.parity.acquire.cta.shared::cta.b64 p, [%1], %2;\n\t" \
        "selp.b32 %0, 1, 0, p;\n\t}" : "=r"(_d) : "r"(_m), "r"(_p) : "memory"); \
    if (!_d) { \
        asm volatile("{\n\t.reg .pred P1;\n\tWL_%=:\n\t" \
            "mbarrier.try_wait.parity.acquire.cta.shared::cta.b64 P1, [%0], %1, 0x989680;\n\t" \
            "@P1 bra.uni WD_%=;\n\tbra.uni WL_%=;\n\tWD_%=:\n\t}" \
            :: "r"(_m), "r"(_p) : "memory"); \
    } } while (0)
#define BULK_G2S(dst, src, sz, mbar) \
    asm volatile("cp.async.bulk.shared::cluster.global.mbarrier::complete_tx::bytes [%0], [%1], %2, [%3];" \
        :: "r"((uint32_t)(dst)), "l"(src), "r"((uint32_t)(sz)), "r"((uint32_t)(mbar)) : "memory")

// ---------------- global barrier (S0 only) ----------------
__device__ __forceinline__ void gridbar(unsigned& epoch) {
    epoch++;
    __threadfence();
    __syncthreads();
    if (blockIdx.x == 0) {
        if (threadIdx.x == 0) g_arrive[0] = epoch;
        for (int b = threadIdx.x; b < (int)gridDim.x; b += blockDim.x) {
            while (g_arrive[b] < epoch) { __nanosleep(16); }
        }
        __syncthreads();
        if (threadIdx.x == 0) { __threadfence(); g_release = epoch; }
    } else {
        if (threadIdx.x == 0) {
            g_arrive[blockIdx.x] = epoch;
            while (g_release < epoch) { __nanosleep(16); }
        }
    }
    __syncthreads();
}

// ---------------- group barrier (32 blocks sharing mg), split arrive/wait ----------------
__device__ __forceinline__ void garrive(int grp, int slot, unsigned& ep) {
    __threadfence();
    __syncthreads();
    ep++;
    if (threadIdx.x == 0) g_flag[grp][slot] = ep;
}
__device__ __forceinline__ void gwait(int grp, unsigned ep) {
    if (threadIdx.x == 0) {
        #pragma unroll 4
        for (int j = 0; j < 32; j++) {
            while (g_flag[grp][j] < ep) { __nanosleep(16); }
        }
        __threadfence();
    }
    __syncthreads();
}

// fast activations (~1e-6 rel err)
__device__ __forceinline__ float sigm(float x) {
    return __fdividef(1.f, 1.f + __expf(-x));
}
__device__ __forceinline__ float tanh_f(float x) {
    float e = __expf(2.f * x);
    return 1.f - __fdividef(2.f, e + 1.f);
}

// pack activation offset: (row 0..511, col) -> packed elem index
__device__ __forceinline__ size_t pk_off(int row, int col) {
    return ((size_t)((col >> 6) * 4 + (row >> 7))) * ABLK + (size_t)(row & 127) * LDA + (col & 63);
}

// ---------------- S0 weight packer (single fp16 plane) ----------------
__device__ void pack_w(const float* __restrict__ W, fp16* __restrict__ dst,
                       int K, int BN, int ntiles, int gated, int gt, int gs)
{
    const int nch = K >> 6;
    const int tot = ntiles * nch * BN * 16;   // float4 units
    for (int i = gt; i < tot; i += gs) {
        int k4 = i & 15;
        int rest = i >> 4;
        int n = rest % BN; rest /= BN;
        int c = rest % nch;
        int nt = rest / nch;
        int row = gated ? ((n >> 5) * HID + nt * 32 + (n & 31)) : (nt * BN + n);
        float4 v = *(const float4*)(W + (size_t)row * K + c * 64 + k4 * 4);
        fp16 h[4];
        h[0] = __float2half_rn(v.x); h[1] = __float2half_rn(v.y);
        h[2] = __float2half_rn(v.z); h[3] = __float2half_rn(v.w);
        size_t d = ((size_t)(nt * nch + c) * BN + n) * LDA + k4 * 4;
        *(uint2*)(dst + d) = *(uint2*)h;
    }
}

// ---------------- pipeline state ----------------
struct Pipe {
    int fullph[NSTAGE];
    int emptyph[NSTAGE];
    int pcnt, ccnt;
};
struct Seg { const fp16 *a, *b; int nch, astr, bstr; };

// ---------------- 6-stage mbar-pipelined wmma GEMM (pure fp16, 1 term) ----------------
template <int NFW>
__device__ void gemm_pk(CFrag (&acc)[2][NFW], char* P, uint32_t pbase,
                        const Seg* segs, int nseg, Pipe& pp)
{
    constexpr int BB = 32 * NFW * 144;                // B plane bytes
    constexpr uint32_t TX = ABLKB + BB;
    const int tid = threadIdx.x;
    const int warp = tid >> 5, lane = tid & 31;
    const int wm = warp >> 1, wn = warp & 1;

    int nt = 0;
    for (int s = 0; s < nseg; s++) nt += segs[s].nch;

    auto do_fill = [&](int gidx) {
        int c = gidx, si = 0;
        while (c >= segs[si].nch) { c -= segs[si].nch; si++; }
        const Seg& S = segs[si];
        int st = pp.pcnt % NSTAGE;
        if (tid == 0) {
            MBAR_WAIT(pbase + 64 + (st << 3), (uint32_t)(pp.emptyph[st] & 1));
            uint32_t d = pbase + 1024 + st * STGMAX;
            uint32_t mb = pbase + (st << 3);
            MBAR_EXPECT(mb, TX);
            BULK_G2S(d,         (const char*)(S.a + (size_t)c * S.astr), ABLKB, mb);
            BULK_G2S(d + ABLKB, (const char*)(S.b + (size_t)c * S.bstr), BB, mb);
        }
        pp.emptyph[st]++;
        pp.pcnt++;
    };

    const int pre = nt < 4 ? nt : 4;
    for (int g = 0; g < pre; g++) do_fill(g);

    for (int i = 0; i < nt; i++) {
        if (i + 4 < nt) do_fill(i + 4);
        const int st = pp.ccnt % NSTAGE;
        MBAR_WAIT(pbase + (st << 3), (uint32_t)(pp.fullph[st] & 1));
        pp.fullph[st]++;
        pp.ccnt++;

        const fp16* sA = (const fp16*)(P + 1024 + st * STGMAX);
        const fp16* sB = sA + ABLK;
        #pragma unroll
        for (int kk = 0; kk < 4; kk++) {
            AFrag a0, a1;
            wmma::load_matrix_sync(a0, sA + (wm * 32 + 0)  * LDA + kk * 16, LDA);
            wmma::load_matrix_sync(a1, sA + (wm * 32 + 16) * LDA + kk * 16, LDA);
            BFrag bf[NFW];
            #pragma unroll
            for (int nf = 0; nf < NFW; nf++)
                wmma::load_matrix_sync(bf[nf], sB + (wn * (16 * NFW) + nf * 16) * LDA + kk * 16, LDA);
            #pragma unroll
            for (int nf = 0; nf < NFW; nf++) {
                wmma::mma_sync(acc[0][nf], a0, bf[nf], acc[0][nf]);
                wmma::mma_sync(acc[1][nf], a1, bf[nf], acc[1][nf]);
            }
        }
        if (lane == 0) MBAR_ARRIVE(pbase + 64 + (st << 3));
    }
}

// ---------------- epilogues (syncthreads at entry: patch aliases stage smem) ----------------
__device__ void lstm_epi(CFrag (&acc)[2][4], char* P, const float* __restrict__ bias,
                         const float* __restrict__ c_in, float* __restrict__ c_out,
                         fp16* __restrict__ hp,
                         int mbase, int jbase)
{
    __syncthreads();                      // lagging warps may still read stages
    float* pf = (float*)(P + 1024);       // patch [128][132]
    const int tid = threadIdx.x, warp = tid >> 5;
    const int wm = warp >> 1, wn = warp & 1;
    #pragma unroll
    for (int i = 0; i < 2; i++)
        #pragma unroll
        for (int nf = 0; nf < 4; nf++)
            wmma::store_matrix_sync(pf + (wm * 32 + i * 16) * 132 + wn * 64 + nf * 16,
                                    acc[i][nf], 132, wmma::mem_row_major);
    __syncthreads();
    #pragma unroll 4
    for (int e = tid; e < 128 * 32; e += NTHREADS) {
        int r = e >> 5, j = e & 31;
        int row = mbase + r, col = jbase + j;
        float iv = pf[r * 132 + j]      + __ldg(bias + col);
        float fv = pf[r * 132 + 32 + j] + __ldg(bias + HID + col);
        float gv = pf[r * 132 + 64 + j] + __ldg(bias + 2 * HID + col);
        float ov = pf[r * 132 + 96 + j] + __ldg(bias + 3 * HID + col);
        float cold = __ldcg(c_in + (size_t)row * HID + col);
        float cn = sigm(fv) * cold + sigm(iv) * tanh_f(gv);
        float hn = sigm(ov) * tanh_f(cn);
        c_out[(size_t)row * HID + col] = cn;
        hp[pk_off(row, col)] = __float2half_rn(hn);
    }
    __syncthreads();
}

template <int NFW>
__device__ void store_epi(CFrag (&acc)[2][NFW], char* P, const float* __restrict__ bias,
                          float* __restrict__ dst, int stride, int mbase, int nbase)
{
    __syncthreads();
    constexpr int BN = 32 * NFW, PS = BN + 4;
    float* pf = (float*)(P + 1024);
    const int tid = threadIdx.x, warp = tid >> 5;
    const int wm = warp >> 1, wn = warp & 1;
    #pragma unroll
    for (int i = 0; i < 2; i++)
        #pragma unroll
        for (int nf = 0; nf < NFW; nf++)
            wmma::store_matrix_sync(pf + (wm * 32 + i * 16) * PS + wn * (16 * NFW) + nf * 16,
                                    acc[i][nf], PS, wmma::mem_row_major);
    __syncthreads();
    for (int e = tid; e < 128 * BN; e += NTHREADS) {
        int r = e / BN, c = e % BN;
        dst[(size_t)(mbase + r) * stride + nbase + c] = pf[r * PS + c] + __ldg(bias + nbase + c);
    }
    __syncthreads();
}

// ---------------- the persistent decoder kernel ----------------
__global__ void __launch_bounds__(NTHREADS, 1) dec_kernel(
    const float* __restrict__ z,     const float* __restrict__ lin1_w, const float* __restrict__ lin1_b,
    const float* __restrict__ ln1_w, const float* __restrict__ ln1_b,
    const float* __restrict__ w_ih0, const float* __restrict__ w_hh0,  const float* __restrict__ b0,
    const float* __restrict__ w_ih1, const float* __restrict__ w_hh1,  const float* __restrict__ b1,
    const float* __restrict__ p1_w,  const float* __restrict__ p1_b,
    const float* __restrict__ pln_w, const float* __restrict__ pln_b,
    const float* __restrict__ p2_w,  const float* __restrict__ p2_b,
    float* __restrict__ out)
{
    extern __shared__ char pool[];
    __shared__ float redA[8], redB[8];
    const int bid = blockIdx.x, nb = gridDim.x, tid = threadIdx.x;
    const int lane = tid & 31;
    const int grp = bid >> 5, slot = bid & 31;   // mg-group id / slot in group
    uint32_t raw = smem_u32(pool);
    uint32_t pbase = (raw + 1023) & ~1023u;
    char* P = pool + (pbase - raw);
    unsigned epoch = g_release;
    unsigned gep = g_flag[grp][slot];            // resume group epoch across replays
    Pipe pp;
    #pragma unroll
    for (int s = 0; s < NSTAGE; s++) { pp.fullph[s] = 0; pp.emptyph[s] = 0; }
    pp.pcnt = 0; pp.ccnt = 0;

    if (tid == 0) {
        #pragma unroll
        for (int s = 0; s < NSTAGE; s++) {
            MBAR_INIT(pbase + (s << 3), 1);       // full: tx-based
            MBAR_INIT(pbase + 64 + (s << 3), 8);  // empty: one arrive per warp
        }
    }
    __syncthreads();
    if (lane == 0) {   // arm all empties (8 warps x lane0 = 8 arrivals each)
        #pragma unroll
        for (int s = 0; s < NSTAGE; s++) MBAR_ARRIVE(pbase + 64 + (s << 3));
    }
    __syncthreads();

    // ---- S0: pack weights (fp16); pack z; transpose p2; zero x  (cross-group -> global barrier)
    {
        int gt = bid * NTHREADS + tid, gs = nb * NTHREADS;
        pack_w(lin1_w, g_lin1p, LATENT, 64, 32, 0, gt, gs);
        pack_w(w_ih0,  g_wih0p, NOUT, 128, 32, 1, gt, gs);
        pack_w(w_hh0,  g_whh0p, HID, 128, 32, 1, gt, gs);
        pack_w(w_ih1,  g_wih1p, HID, 128, 32, 1, gt, gs);
        pack_w(w_hh1,  g_whh1p, HID, 128, 32, 1, gt, gs);
        pack_w(p1_w,   g_p1p,   HID, 32, 32, 0, gt, gs);
        for (int i = gt; i < 4 * 4 * 128 * 16; i += gs) {
            int k4 = i & 15, r = (i >> 4) & 127, mg = (i >> 11) & 3, c = i >> 13;
            float4 v = *(const float4*)(z + (size_t)(mg * 128 + r) * LATENT + c * 64 + k4 * 4);
            fp16 h[4];
            h[0] = __float2half_rn(v.x); h[1] = __float2half_rn(v.y);
            h[2] = __float2half_rn(v.z); h[3] = __float2half_rn(v.w);
            size_t d = (size_t)(c * 4 + mg) * ABLK + (size_t)r * LDA + k4 * 4;
            *(uint2*)(g_zp + d) = *(uint2*)h;
        }
        for (int i = gt; i < 256 * 128; i += gs) {
            int o = i & 127, kq = i >> 7;
            g_p2q[i] = *(const float4*)(p2_w + (size_t)o * HID + kq * 4);
        }
        for (int i = gt; i < 2 * 4 * ABLK; i += gs) {
            g_xp[i] = __float2half_rn(0.f);
        }
    }
    gridbar(epoch);

    // ---- S1: u = z @ lin1_w^T + lin1_b  (512 x 2048): 128 tiles of 128x64
    {
        int mg = grp, nt = slot;
        CFrag acc[2][2];
        #pragma unroll
        for (int i = 0; i < 2; i++) { wmma::fill_fragment(acc[i][0], 0.f); wmma::fill_fragment(acc[i][1], 0.f); }
        Seg sg[1] = {{g_zp + (size_t)mg * ABLK,
                      g_lin1p + (size_t)nt * 4 * 4608,
                      4, 4 * ABLK, 4608}};
        gemm_pk<2>(acc, P, pbase, sg, 1, pp);
        store_epi<2>(acc, P, lin1_b, g_u, 2 * HID, mg << 7, nt << 6);
    }
    garrive(grp, slot, gep); gwait(grp, gep);

    // ---- S2: LayerNorm(2048) + gelu -> h0/c0 (both cells), 2 rows per pass
    {
        float* pf = (float*)(P + 1024);
        const int g = tid >> 7, lt = tid & 127, w4 = (tid >> 5) & 3;
        {
            int grp2 = bid;
            for (int pass = 0; pass < 2; pass++) {
                int row = (grp2 << 2) + pass * 2 + g;
                const float* urow = g_u + (size_t)row * 2 * HID;
                float ls = 0.f, lq = 0.f;
                #pragma unroll
                for (int u = 0; u < 16; u++) {
                    float v = __ldcg(urow + u * 128 + lt);
                    pf[g * 2048 + u * 128 + lt] = v;
                    ls += v; lq += v * v;
                }
                #pragma unroll
                for (int o = 16; o > 0; o >>= 1) {
                    ls += __shfl_down_sync(0xffffffffu, ls, o);
                    lq += __shfl_down_sync(0xffffffffu, lq, o);
                }
                if (lane == 0) { redA[g * 4 + w4] = ls; redB[g * 4 + w4] = lq; }
                __syncthreads();
                float S = redA[g * 4] + redA[g * 4 + 1] + redA[g * 4 + 2] + redA[g * 4 + 3];
                float Q = redB[g * 4] + redB[g * 4 + 1] + redB[g * 4 + 2] + redB[g * 4 + 3];
                float mu = S * (1.f / 2048.f);
                float rstd = rsqrtf(Q * (1.f / 2048.f) - mu * mu + 1e-5f);
                #pragma unroll
                for (int u = 0; u < 16; u++) {
                    int i = u * 128 + lt;
                    float v = (pf[g * 2048 + i] - mu) * rstd * __ldg(ln1_w + i) + __ldg(ln1_b + i);
                    float ge = v * normcdff(v);
                    if (i < HID) {
                        fp16 hv = __float2half_rn(ge);
                        size_t off = pk_off(row, i);
                        g_h1p[0][off] = hv;
                        g_h2p[0][off] = hv;
                    } else {
                        g_c1[0][(size_t)row * HID + i - HID] = ge;
                        g_c2[0][(size_t)row * HID + i - HID] = ge;
                    }
                }
                __syncthreads();
            }
        }
    }
    garrive(grp, slot, gep); gwait(grp, gep);

    // ---- main sequential loop (split group barriers; 2 of 4 waits hidden behind GEMMs)
    for (int s = 0; s < SEQL; s++) {
        const int pi = s & 1, po = pi ^ 1;
        const int mg = grp, ntl = slot;

        // P1: seg_h (no dep on P4) -> wait x -> seg_x -> epilogue -> arrive
        {
            CFrag acc[2][4];
            #pragma unroll
            for (int i = 0; i < 2; i++)
                #pragma unroll
                for (int j = 0; j < 4; j++) wmma::fill_fragment(acc[i][j], 0.f);
            Seg sgh[1] = {{g_h1p[pi] + (size_t)mg * ABLK,
                           g_whh0p + (size_t)ntl * 16 * 9216,
                           16, 4 * ABLK, 9216}};
            gemm_pk<4>(acc, P, pbase, sgh, 1, pp);
            gwait(grp, gep);                    // x from P4(s-1) ready (no-op at s=0)
            Seg sgx[1] = {{g_xp + (size_t)mg * ABLK,
                           g_wih0p + (size_t)ntl * 2 * 9216,
                           2, 4 * ABLK, 9216}};
            gemm_pk<4>(acc, P, pbase, sgx, 1, pp);
            lstm_epi(acc, P, b0, g_c1[pi], g_c1[po], g_h1p[po], mg << 7, ntl << 5);
        }
        garrive(grp, slot, gep);

        // P2: seg_h2 (no dep on P1) -> wait h1 -> seg_h1 -> epilogue -> arrive
        {
            CFrag acc[2][4];
            #pragma unroll
            for (int i = 0; i < 2; i++)
                #pragma unroll
                for (int j = 0; j < 4; j++) wmma::fill_fragment(acc[i][j], 0.f);
            Seg sg2[1] = {{g_h2p[pi] + (size_t)mg * ABLK,
                           g_whh1p + (size_t)ntl * 16 * 9216,
                           16, 4 * ABLK, 9216}};
            gemm_pk<4>(acc, P, pbase, sg2, 1, pp);
            gwait(grp, gep);                    // h1_new ready
            Seg sg1[1] = {{g_h1p[po] + (size_t)mg * ABLK,
                           g_wih1p + (size_t)ntl * 16 * 9216,
                           16, 4 * ABLK, 9216}};
            gemm_pk<4>(acc, P, pbase, sg1, 1, pp);
            lstm_epi(acc, P, b1, g_c2[pi], g_c2[po], g_h2p[po], mg << 7, ntl << 5);
        }
        garrive(grp, slot, gep);

        // P3: wait h2 -> t = h2_new @ p1_w^T + p1_b -> arrive
        gwait(grp, gep);
        {
            CFrag acc[2][1];
            wmma::fill_fragment(acc[0][0], 0.f);
            wmma::fill_fragment(acc[1][0], 0.f);
            Seg sg[1] = {{g_h2p[po] + (size_t)mg * ABLK,
                          g_p1p + (size_t)ntl * 16 * 2304,
                          16, 4 * ABLK, 2304}};
            gemm_pk<1>(acc, P, pbase, sg, 1, pp);
            store_epi<1>(acc, P, p1_b, g_t, HID, mg << 7, ntl << 5);
        }
        garrive(grp, slot, gep);

        // P4: wait t -> LayerNorm + gelu + GEMV -> x, out -> arrive
        gwait(grp, gep);
        {
            float* pf = (float*)(P + 1024);        // [4][1024] gelu vals + [8][128] partials
            float* psum = pf + 4096;
            const int g = tid >> 7, lt = tid & 127, w4 = (tid >> 5) & 3;
            const int grp2 = bid;
            for (int pass = 0; pass < 2; pass++) {
                int rr = pass * 2 + g;
                int row = (grp2 << 2) + rr;
                const float* trow = g_t + (size_t)row * HID;
                float vb[8]; float ls = 0.f, lq = 0.f;
                #pragma unroll
                for (int u = 0; u < 8; u++) {
                    float v = __ldcg(trow + u * 128 + lt);
                    vb[u] = v; ls += v; lq += v * v;
                }
                #pragma unroll
                for (int o = 16; o > 0; o >>= 1) {
                    ls += __shfl_down_sync(0xffffffffu, ls, o);
                    lq += __shfl_down_sync(0xffffffffu, lq, o);
                }
                if (lane == 0) { redA[g * 4 + w4] = ls; redB[g * 4 + w4] = lq; }
                __syncthreads();
                float S = redA[g * 4] + redA[g * 4 + 1] + redA[g * 4 + 2] + redA[g * 4 + 3];
                float Q = redB[g * 4] + redB[g * 4 + 1] + redB[g * 4 + 2] + redB[g * 4 + 3];
                float mu = S * (1.f / 1024.f);
                float rstd = rsqrtf(Q * (1.f / 1024.f) - mu * mu + 1e-5f);
                #pragma unroll
                for (int u = 0; u < 8; u++) {
                    int i = u * 128 + lt;
                    float v = (vb[u] - mu) * rstd * __ldg(pln_w + i) + __ldg(pln_b + i);
                    pf[rr * 1024 + i] = v * normcdff(v);
                }
                __syncthreads();
            }
            {
                float a0 = 0.f, a1 = 0.f, a2 = 0.f, a3 = 0.f;
                const int kq0 = g * 128;
                #pragma unroll 2
                for (int kq = 0; kq < 128; kq++) {
                    float4 wv = g_p2q[(size_t)(kq0 + kq) * 128 + lt];
                    float4 g0 = *(const float4*)(pf + 0 * 1024 + (kq0 + kq) * 4);
                    float4 g1 = *(const float4*)(pf + 1 * 1024 + (kq0 + kq) * 4);
                    float4 g2 = *(const float4*)(pf + 2 * 1024 + (kq0 + kq) * 4);
                    float4 g3 = *(const float4*)(pf + 3 * 1024 + (kq0 + kq) * 4);
                    a0 += g0.x * wv.x + g0.y * wv.y + g0.z * wv.z + g0.w * wv.w;
                    a1 += g1.x * wv.x + g1.y * wv.y + g1.z * wv.z + g1.w * wv.w;
                    a2 += g2.x * wv.x + g2.y * wv.y + g2.z * wv.z + g2.w * wv.w;
                    a3 += g3.x * wv.x + g3.y * wv.y + g3.z * wv.z + g3.w * wv.w;
                }
                psum[(0 * 2 + g) * 128 + lt] = a0;
                psum[(1 * 2 + g) * 128 + lt] = a1;
                psum[(2 * 2 + g) * 128 + lt] = a2;
                psum[(3 * 2 + g) * 128 + lt] = a3;
            }
            __syncthreads();
            for (int idx = tid; idx < 512; idx += NTHREADS) {
                int r = idx >> 7, o = idx & 127;
                int row = (grp2 << 2) + r;
                float y = psum[(r * 2) * 128 + o] + psum[(r * 2 + 1) * 128 + o] + __ldg(p2_b + o);
                g_xp[pk_off(row, o)] = __float2half_rn(y);
                out[(size_t)row * SEQL * NOUT + s * NOUT + o] = y;
            }
            __syncthreads();
        }
        garrive(grp, slot, gep);
    }
}

// ---------------- launch ----------------
extern "C" void kernel_launch(void* const* d_in, const int* in_sizes, int n_in,
                              void* d_out, int out_size) {
    (void)in_sizes; (void)n_in; (void)out_size;
    cudaFuncSetAttribute(dec_kernel, cudaFuncAttributeMaxDynamicSharedMemorySize, SMEM_BYTES);

    const float* z      = (const float*)d_in[0];
    const float* lin1_w = (const float*)d_in[1];
    const float* lin1_b = (const float*)d_in[2];
    const float* ln1_w  = (const float*)d_in[3];
    const float* ln1_b  = (const float*)d_in[4];
    const float* w_ih0  = (const float*)d_in[5];
    const float* w_hh0  = (const float*)d_in[6];
    const float* b0     = (const float*)d_in[7];
    const float* w_ih1  = (const float*)d_in[8];
    const float* w_hh1  = (const float*)d_in[9];
    const float* b1     = (const float*)d_in[10];
    const float* p1_w   = (const float*)d_in[11];
    const float* p1_b   = (const float*)d_in[12];
    const float* pln_w  = (const float*)d_in[13];
    const float* pln_b  = (const float*)d_in[14];
    const float* p2_w   = (const float*)d_in[15];
    const float* p2_b   = (const float*)d_in[16];

    dec_kernel<<<NBLOCKS, NTHREADS, SMEM_BYTES>>>(
        z, lin1_w, lin1_b, ln1_w, ln1_b,
        w_ih0, w_hh0, b0, w_ih1, w_hh1, b1,
        p1_w, p1_b, pln_w, pln_b, p2_w, p2_b,
        (float*)d_out);
}

// round 13
// speedup vs baseline: 1.2086x; 1.2086x over previous
#include <cuda_runtime.h>
#include <cuda_fp16.h>
#include <mma.h>
#include <math.h>
#include <stdint.h>

using namespace nvcuda;
using fp16 = __half;

#define LATENT 256
#define HID    1024
#define NOUT   128
#define SEQL   96

#define NTHREADS 256
#define NBLOCKS  128
#define LDA    72
#define ABLK   9216          // elems per 128x72 block
#define ABLKB  18432         // bytes per 128x72 fp16 block
#define NSTAGE 6
#define STGMAX 36864         // bytes per stage buffer (A + B at NFW=4)

// smem: 1024 align slack + 1024 hdr (mbars) + 6 stage buffers = 223232
#define SMEM_BYTES (1024 + 1024 + NSTAGE * STGMAX)

// ---------------- device scratch (packed layouts) ----------------
__device__ __align__(16) fp16 g_lin1p[32 * 4 * 4608];     // BN=64, K=256
__device__ __align__(16) fp16 g_wih0p[32 * 2 * 9216];     // BN=128 gated, K=128
__device__ __align__(16) fp16 g_whh0p[32 * 16 * 9216];    // BN=128 gated, K=1024
__device__ __align__(16) fp16 g_wih1p[32 * 16 * 9216];
__device__ __align__(16) fp16 g_whh1p[32 * 16 * 9216];
__device__ __align__(16) fp16 g_p1p[32 * 16 * 2304];      // BN=32, K=1024
__device__ __align__(16) float4 g_p2q[256 * 128];         // p2_w transposed k-quad major
// activations: single fp16 plane, packed [kchunk][mgroup][128 x 72]
__device__ __align__(16) fp16 g_zp[4 * 4 * 9216];
__device__ __align__(16) fp16 g_xp[2 * 4 * 9216];
__device__ __align__(16) fp16 g_h1p[2][16 * 4 * 9216];    // [pingpong]
__device__ __align__(16) fp16 g_h2p[2][16 * 4 * 9216];
__device__ float g_c1[2][512 * HID];
__device__ float g_c2[2][512 * HID];
__device__ float g_u[512 * 2 * HID];
__device__ float g_t[512 * HID];
// barriers
__device__ volatile unsigned g_arrive[256];               // global (S0 only)
__device__ volatile unsigned g_release;
__device__ __align__(128) volatile unsigned g_flag[4][32]; // per-mg-group flags

typedef wmma::fragment<wmma::accumulator, 16, 16, 16, float> CFrag;
typedef wmma::fragment<wmma::matrix_a, 16, 16, 16, fp16, wmma::row_major> AFrag;
typedef wmma::fragment<wmma::matrix_b, 16, 16, 16, fp16, wmma::col_major> BFrag;

// ---------------- PTX helpers ----------------
__device__ __forceinline__ uint32_t smem_u32(const void* p) {
    uint32_t a;
    asm("{ .reg .u64 t; cvta.to.shared.u64 t, %1; cvt.u32.u64 %0, t; }" : "=r"(a) : "l"(p));
    return a;
}
#define MBAR_INIT(a, c) \
    asm volatile("mbarrier.init.shared.b64 [%0], %1;" :: "r"(a), "r"((uint32_t)(c)) : "memory")
#define MBAR_EXPECT(a, n) \
    asm volatile("mbarrier.arrive.expect_tx.shared.b64 _, [%0], %1;" :: "r"(a), "r"((uint32_t)(n)) : "memory")
#define MBAR_ARRIVE(a) \
    asm volatile("mbarrier.arrive.shared.b64 _, [%0];" :: "r"((uint32_t)(a)) : "memory")
#define MBAR_WAIT(a, par) do { \
    uint32_t _m = (a), _p = (par), _d; \
    asm volatile("{\n\t.reg .pred p;\n\t" \
        "mbarrier.try_wait.parity.acquire.cta.shared::cta.b64 p, [%1], %2;\n\t" \
        "selp.b32 %0, 1, 0, p;\n\t}" : "=r"(_d) : "r"(_m), "r"(_p) : "memory"); \
    if (!_d) { \
        asm volatile("{\n\t.reg .pred P1;\n\tWL_%=:\n\t" \
            "mbarrier.try_wait.parity.acquire.cta.shared::cta.b64 P1, [%0], %1, 0x989680;\n\t" \
            "@P1 bra.uni WD_%=;\n\tbra.uni WL_%=;\n\tWD_%=:\n\t}" \
            :: "r"(_m), "r"(_p) : "memory"); \
    } } while (0)
#define BULK_G2S(dst, src, sz, mbar) \
    asm volatile("cp.async.bulk.shared::cluster.global.mbarrier::complete_tx::bytes [%0], [%1], %2, [%3];" \
        :: "r"((uint32_t)(dst)), "l"(src), "r"((uint32_t)(sz)), "r"((uint32_t)(mbar)) : "memory")

// ---------------- global barrier (S0 only) ----------------
__device__ __forceinline__ void gridbar(unsigned& epoch) {
    epoch++;
    __threadfence();
    __syncthreads();
    if (blockIdx.x == 0) {
        if (threadIdx.x == 0) g_arrive[0] = epoch;
        for (int b = threadIdx.x; b < (int)gridDim.x; b += blockDim.x) {
            while (g_arrive[b] < epoch) { __nanosleep(16); }
        }
        __syncthreads();
        if (threadIdx.x == 0) { __threadfence(); g_release = epoch; }
    } else {
        if (threadIdx.x == 0) {
            g_arrive[blockIdx.x] = epoch;
            while (g_release < epoch) { __nanosleep(16); }
        }
    }
    __syncthreads();
}

// ---------------- group barrier (32 blocks sharing mg), split arrive/wait ----------------
__device__ __forceinline__ void garrive(int grp, int slot, unsigned& ep) {
    __threadfence();
    __syncthreads();
    ep++;
    if (threadIdx.x == 0) g_flag[grp][slot] = ep;
}
// parallel poll: lanes 0..31 each own one flag (all in one 128B line)
__device__ __forceinline__ void gwait(int grp, unsigned ep) {
    if (threadIdx.x < 32) {
        while (g_flag[grp][threadIdx.x] < ep) { __nanosleep(16); }
        __threadfence();
    }
    __syncthreads();
}

// fast activations (~1e-6 rel err)
__device__ __forceinline__ float sigm(float x) {
    return __fdividef(1.f, 1.f + __expf(-x));
}
__device__ __forceinline__ float tanh_f(float x) {
    float e = __expf(2.f * x);
    return 1.f - __fdividef(2.f, e + 1.f);
}

// pack activation offset: (row 0..511, col) -> packed elem index
__device__ __forceinline__ size_t pk_off(int row, int col) {
    return ((size_t)((col >> 6) * 4 + (row >> 7))) * ABLK + (size_t)(row & 127) * LDA + (col & 63);
}

// ---------------- S0 weight packer (single fp16 plane) ----------------
__device__ void pack_w(const float* __restrict__ W, fp16* __restrict__ dst,
                       int K, int BN, int ntiles, int gated, int gt, int gs)
{
    const int nch = K >> 6;
    const int tot = ntiles * nch * BN * 16;   // float4 units
    for (int i = gt; i < tot; i += gs) {
        int k4 = i & 15;
        int rest = i >> 4;
        int n = rest % BN; rest /= BN;
        int c = rest % nch;
        int nt = rest / nch;
        int row = gated ? ((n >> 5) * HID + nt * 32 + (n & 31)) : (nt * BN + n);
        float4 v = *(const float4*)(W + (size_t)row * K + c * 64 + k4 * 4);
        fp16 h[4];
        h[0] = __float2half_rn(v.x); h[1] = __float2half_rn(v.y);
        h[2] = __float2half_rn(v.z); h[3] = __float2half_rn(v.w);
        size_t d = ((size_t)(nt * nch + c) * BN + n) * LDA + k4 * 4;
        *(uint2*)(dst + d) = *(uint2*)h;
    }
}

// ---------------- pipeline state ----------------
struct Pipe {
    int fullph[NSTAGE];
    int emptyph[NSTAGE];
    int pcnt, ccnt;
};
struct Seg { const fp16 *a, *b; int nch, astr, bstr; };

// ---------------- 6-stage mbar-pipelined wmma GEMM (pure fp16, 1 term) ----------------
template <int NFW>
__device__ void gemm_pk(CFrag (&acc)[2][NFW], char* P, uint32_t pbase,
                        const Seg* segs, int nseg, Pipe& pp)
{
    constexpr int BB = 32 * NFW * 144;                // B plane bytes
    constexpr uint32_t TX = ABLKB + BB;
    const int tid = threadIdx.x;
    const int warp = tid >> 5, lane = tid & 31;
    const int wm = warp >> 1, wn = warp & 1;

    int nt = 0;
    for (int s = 0; s < nseg; s++) nt += segs[s].nch;

    auto do_fill = [&](int gidx) {
        int c = gidx, si = 0;
        while (c >= segs[si].nch) { c -= segs[si].nch; si++; }
        const Seg& S = segs[si];
        int st = pp.pcnt % NSTAGE;
        if (tid == 0) {
            MBAR_WAIT(pbase + 64 + (st << 3), (uint32_t)(pp.emptyph[st] & 1));
            uint32_t d = pbase + 1024 + st * STGMAX;
            uint32_t mb = pbase + (st << 3);
            MBAR_EXPECT(mb, TX);
            BULK_G2S(d,         (const char*)(S.a + (size_t)c * S.astr), ABLKB, mb);
            BULK_G2S(d + ABLKB, (const char*)(S.b + (size_t)c * S.bstr), BB, mb);
        }
        pp.emptyph[st]++;
        pp.pcnt++;
    };

    const int pre = nt < 4 ? nt : 4;
    for (int g = 0; g < pre; g++) do_fill(g);

    for (int i = 0; i < nt; i++) {
        if (i + 4 < nt) do_fill(i + 4);
        const int st = pp.ccnt % NSTAGE;
        MBAR_WAIT(pbase + (st << 3), (uint32_t)(pp.fullph[st] & 1));
        pp.fullph[st]++;
        pp.ccnt++;

        const fp16* sA = (const fp16*)(P + 1024 + st * STGMAX);
        const fp16* sB = sA + ABLK;
        #pragma unroll
        for (int kk = 0; kk < 4; kk++) {
            AFrag a0, a1;
            wmma::load_matrix_sync(a0, sA + (wm * 32 + 0)  * LDA + kk * 16, LDA);
            wmma::load_matrix_sync(a1, sA + (wm * 32 + 16) * LDA + kk * 16, LDA);
            BFrag bf[NFW];
            #pragma unroll
            for (int nf = 0; nf < NFW; nf++)
                wmma::load_matrix_sync(bf[nf], sB + (wn * (16 * NFW) + nf * 16) * LDA + kk * 16, LDA);
            #pragma unroll
            for (int nf = 0; nf < NFW; nf++) {
                wmma::mma_sync(acc[0][nf], a0, bf[nf], acc[0][nf]);
                wmma::mma_sync(acc[1][nf], a1, bf[nf], acc[1][nf]);
            }
        }
        if (lane == 0) MBAR_ARRIVE(pbase + 64 + (st << 3));
    }
}

// ---------------- epilogues (syncthreads at entry: patch aliases stage smem) ----------------
__device__ void lstm_epi(CFrag (&acc)[2][4], char* P, const float* __restrict__ bias,
                         const float* __restrict__ c_in, float* __restrict__ c_out,
                         fp16* __restrict__ hp,
                         int mbase, int jbase)
{
    __syncthreads();                      // lagging warps may still read stages
    float* pf = (float*)(P + 1024);       // patch [128][132]
    const int tid = threadIdx.x, warp = tid >> 5;
    const int wm = warp >> 1, wn = warp & 1;
    #pragma unroll
    for (int i = 0; i < 2; i++)
        #pragma unroll
        for (int nf = 0; nf < 4; nf++)
            wmma::store_matrix_sync(pf + (wm * 32 + i * 16) * 132 + wn * 64 + nf * 16,
                                    acc[i][nf], 132, wmma::mem_row_major);
    __syncthreads();
    #pragma unroll 4
    for (int e = tid; e < 128 * 32; e += NTHREADS) {
        int r = e >> 5, j = e & 31;
        int row = mbase + r, col = jbase + j;
        float iv = pf[r * 132 + j]      + __ldg(bias + col);
        float fv = pf[r * 132 + 32 + j] + __ldg(bias + HID + col);
        float gv = pf[r * 132 + 64 + j] + __ldg(bias + 2 * HID + col);
        float ov = pf[r * 132 + 96 + j] + __ldg(bias + 3 * HID + col);
        float cold = __ldcg(c_in + (size_t)row * HID + col);
        float cn = sigm(fv) * cold + sigm(iv) * tanh_f(gv);
        float hn = sigm(ov) * tanh_f(cn);
        c_out[(size_t)row * HID + col] = cn;
        hp[pk_off(row, col)] = __float2half_rn(hn);
    }
    __syncthreads();
}

template <int NFW>
__device__ void store_epi(CFrag (&acc)[2][NFW], char* P, const float* __restrict__ bias,
                          float* __restrict__ dst, int stride, int mbase, int nbase)
{
    __syncthreads();
    constexpr int BN = 32 * NFW, PS = BN + 4;
    float* pf = (float*)(P + 1024);
    const int tid = threadIdx.x, warp = tid >> 5;
    const int wm = warp >> 1, wn = warp & 1;
    #pragma unroll
    for (int i = 0; i < 2; i++)
        #pragma unroll
        for (int nf = 0; nf < NFW; nf++)
            wmma::store_matrix_sync(pf + (wm * 32 + i * 16) * PS + wn * (16 * NFW) + nf * 16,
                                    acc[i][nf], PS, wmma::mem_row_major);
    __syncthreads();
    for (int e = tid; e < 128 * BN; e += NTHREADS) {
        int r = e / BN, c = e % BN;
        dst[(size_t)(mbase + r) * stride + nbase + c] = pf[r * PS + c] + __ldg(bias + nbase + c);
    }
    __syncthreads();
}

// ---------------- the persistent decoder kernel ----------------
__global__ void __launch_bounds__(NTHREADS, 1) dec_kernel(
    const float* __restrict__ z,     const float* __restrict__ lin1_w, const float* __restrict__ lin1_b,
    const float* __restrict__ ln1_w, const float* __restrict__ ln1_b,
    const float* __restrict__ w_ih0, const float* __restrict__ w_hh0,  const float* __restrict__ b0,
    const float* __restrict__ w_ih1, const float* __restrict__ w_hh1,  const float* __restrict__ b1,
    const float* __restrict__ p1_w,  const float* __restrict__ p1_b,
    const float* __restrict__ pln_w, const float* __restrict__ pln_b,
    const float* __restrict__ p2_w,  const float* __restrict__ p2_b,
    float* __restrict__ out)
{
    extern __shared__ char pool[];
    __shared__ float redA[8], redB[8];
    const int bid = blockIdx.x, nb = gridDim.x, tid = threadIdx.x;
    const int lane = tid & 31;
    const int grp = bid >> 5, slot = bid & 31;   // mg-group id / slot in group
    uint32_t raw = smem_u32(pool);
    uint32_t pbase = (raw + 1023) & ~1023u;
    char* P = pool + (pbase - raw);
    unsigned epoch = g_release;
    unsigned gep = g_flag[grp][slot];            // resume group epoch across replays
    Pipe pp;
    #pragma unroll
    for (int s = 0; s < NSTAGE; s++) { pp.fullph[s] = 0; pp.emptyph[s] = 0; }
    pp.pcnt = 0; pp.ccnt = 0;

    if (tid == 0) {
        #pragma unroll
        for (int s = 0; s < NSTAGE; s++) {
            MBAR_INIT(pbase + (s << 3), 1);       // full: tx-based
            MBAR_INIT(pbase + 64 + (s << 3), 8);  // empty: one arrive per warp
        }
    }
    __syncthreads();
    if (lane == 0) {   // arm all empties (8 warps x lane0 = 8 arrivals each)
        #pragma unroll
        for (int s = 0; s < NSTAGE; s++) MBAR_ARRIVE(pbase + 64 + (s << 3));
    }
    __syncthreads();

    // ---- S0: pack weights (fp16); pack z; transpose p2; zero x  (cross-group -> global barrier)
    {
        int gt = bid * NTHREADS + tid, gs = nb * NTHREADS;
        pack_w(lin1_w, g_lin1p, LATENT, 64, 32, 0, gt, gs);
        pack_w(w_ih0,  g_wih0p, NOUT, 128, 32, 1, gt, gs);
        pack_w(w_hh0,  g_whh0p, HID, 128, 32, 1, gt, gs);
        pack_w(w_ih1,  g_wih1p, HID, 128, 32, 1, gt, gs);
        pack_w(w_hh1,  g_whh1p, HID, 128, 32, 1, gt, gs);
        pack_w(p1_w,   g_p1p,   HID, 32, 32, 0, gt, gs);
        for (int i = gt; i < 4 * 4 * 128 * 16; i += gs) {
            int k4 = i & 15, r = (i >> 4) & 127, mg = (i >> 11) & 3, c = i >> 13;
            float4 v = *(const float4*)(z + (size_t)(mg * 128 + r) * LATENT + c * 64 + k4 * 4);
            fp16 h[4];
            h[0] = __float2half_rn(v.x); h[1] = __float2half_rn(v.y);
            h[2] = __float2half_rn(v.z); h[3] = __float2half_rn(v.w);
            size_t d = (size_t)(c * 4 + mg) * ABLK + (size_t)r * LDA + k4 * 4;
            *(uint2*)(g_zp + d) = *(uint2*)h;
        }
        for (int i = gt; i < 256 * 128; i += gs) {
            int o = i & 127, kq = i >> 7;
            g_p2q[i] = *(const float4*)(p2_w + (size_t)o * HID + kq * 4);
        }
        for (int i = gt; i < 2 * 4 * ABLK; i += gs) {
            g_xp[i] = __float2half_rn(0.f);
        }
    }
    gridbar(epoch);

    // ---- S1: u = z @ lin1_w^T + lin1_b  (512 x 2048): 128 tiles of 128x64
    {
        int mg = grp, nt = slot;
        CFrag acc[2][2];
        #pragma unroll
        for (int i = 0; i < 2; i++) { wmma::fill_fragment(acc[i][0], 0.f); wmma::fill_fragment(acc[i][1], 0.f); }
        Seg sg[1] = {{g_zp + (size_t)mg * ABLK,
                      g_lin1p + (size_t)nt * 4 * 4608,
                      4, 4 * ABLK, 4608}};
        gemm_pk<2>(acc, P, pbase, sg, 1, pp);
        store_epi<2>(acc, P, lin1_b, g_u, 2 * HID, mg << 7, nt << 6);
    }
    garrive(grp, slot, gep); gwait(grp, gep);

    // ---- S2: LayerNorm(2048) + gelu -> h0/c0 (both cells), 2 rows per pass
    {
        float* pf = (float*)(P + 1024);
        const int g = tid >> 7, lt = tid & 127, w4 = (tid >> 5) & 3;
        {
            int grp2 = bid;
            for (int pass = 0; pass < 2; pass++) {
                int row = (grp2 << 2) + pass * 2 + g;
                const float* urow = g_u + (size_t)row * 2 * HID;
                float ls = 0.f, lq = 0.f;
                #pragma unroll
                for (int u = 0; u < 16; u++) {
                    float v = __ldcg(urow + u * 128 + lt);
                    pf[g * 2048 + u * 128 + lt] = v;
                    ls += v; lq += v * v;
                }
                #pragma unroll
                for (int o = 16; o > 0; o >>= 1) {
                    ls += __shfl_down_sync(0xffffffffu, ls, o);
                    lq += __shfl_down_sync(0xffffffffu, lq, o);
                }
                if (lane == 0) { redA[g * 4 + w4] = ls; redB[g * 4 + w4] = lq; }
                __syncthreads();
                float S = redA[g * 4] + redA[g * 4 + 1] + redA[g * 4 + 2] + redA[g * 4 + 3];
                float Q = redB[g * 4] + redB[g * 4 + 1] + redB[g * 4 + 2] + redB[g * 4 + 3];
                float mu = S * (1.f / 2048.f);
                float rstd = rsqrtf(Q * (1.f / 2048.f) - mu * mu + 1e-5f);
                #pragma unroll
                for (int u = 0; u < 16; u++) {
                    int i = u * 128 + lt;
                    float v = (pf[g * 2048 + i] - mu) * rstd * __ldg(ln1_w + i) + __ldg(ln1_b + i);
                    float ge = v * normcdff(v);
                    if (i < HID) {
                        fp16 hv = __float2half_rn(ge);
                        size_t off = pk_off(row, i);
                        g_h1p[0][off] = hv;
                        g_h2p[0][off] = hv;
                    } else {
                        g_c1[0][(size_t)row * HID + i - HID] = ge;
                        g_c2[0][(size_t)row * HID + i - HID] = ge;
                    }
                }
                __syncthreads();
            }
        }
    }
    garrive(grp, slot, gep); gwait(grp, gep);

    // ---- main sequential loop (split group barriers; 2 of 4 waits hidden behind GEMMs)
    for (int s = 0; s < SEQL; s++) {
        const int pi = s & 1, po = pi ^ 1;
        const int mg = grp, ntl = slot;

        // P1: seg_h (no dep on P4) -> wait x -> seg_x -> epilogue -> arrive
        {
            CFrag acc[2][4];
            #pragma unroll
            for (int i = 0; i < 2; i++)
                #pragma unroll
                for (int j = 0; j < 4; j++) wmma::fill_fragment(acc[i][j], 0.f);
            Seg sgh[1] = {{g_h1p[pi] + (size_t)mg * ABLK,
                           g_whh0p + (size_t)ntl * 16 * 9216,
                           16, 4 * ABLK, 9216}};
            gemm_pk<4>(acc, P, pbase, sgh, 1, pp);
            gwait(grp, gep);                    // x from P4(s-1) ready (no-op at s=0)
            Seg sgx[1] = {{g_xp + (size_t)mg * ABLK,
                           g_wih0p + (size_t)ntl * 2 * 9216,
                           2, 4 * ABLK, 9216}};
            gemm_pk<4>(acc, P, pbase, sgx, 1, pp);
            lstm_epi(acc, P, b0, g_c1[pi], g_c1[po], g_h1p[po], mg << 7, ntl << 5);
        }
        garrive(grp, slot, gep);

        // P2: seg_h2 (no dep on P1) -> wait h1 -> seg_h1 -> epilogue -> arrive
        {
            CFrag acc[2][4];
            #pragma unroll
            for (int i = 0; i < 2; i++)
                #pragma unroll
                for (int j = 0; j < 4; j++) wmma::fill_fragment(acc[i][j], 0.f);
            Seg sg2[1] = {{g_h2p[pi] + (size_t)mg * ABLK,
                           g_whh1p + (size_t)ntl * 16 * 9216,
                           16, 4 * ABLK, 9216}};
            gemm_pk<4>(acc, P, pbase, sg2, 1, pp);
            gwait(grp, gep);                    // h1_new ready
            Seg sg1[1] = {{g_h1p[po] + (size_t)mg * ABLK,
                           g_wih1p + (size_t)ntl * 16 * 9216,
                           16, 4 * ABLK, 9216}};
            gemm_pk<4>(acc, P, pbase, sg1, 1, pp);
            lstm_epi(acc, P, b1, g_c2[pi], g_c2[po], g_h2p[po], mg << 7, ntl << 5);
        }
        garrive(grp, slot, gep);

        // P3: wait h2 -> t = h2_new @ p1_w^T + p1_b -> arrive
        gwait(grp, gep);
        {
            CFrag acc[2][1];
            wmma::fill_fragment(acc[0][0], 0.f);
            wmma::fill_fragment(acc[1][0], 0.f);
            Seg sg[1] = {{g_h2p[po] + (size_t)mg * ABLK,
                          g_p1p + (size_t)ntl * 16 * 2304,
                          16, 4 * ABLK, 2304}};
            gemm_pk<1>(acc, P, pbase, sg, 1, pp);
            store_epi<1>(acc, P, p1_b, g_t, HID, mg << 7, ntl << 5);
        }
        garrive(grp, slot, gep);

        // P4: wait t -> LayerNorm + gelu + GEMV -> x, out -> arrive
        gwait(grp, gep);
        {
            float* pf = (float*)(P + 1024);        // [4][1024] gelu vals + [8][128] partials
            float* psum = pf + 4096;
            const int g = tid >> 7, lt = tid & 127, w4 = (tid >> 5) & 3;
            const int grp2 = bid;
            for (int pass = 0; pass < 2; pass++) {
                int rr = pass * 2 + g;
                int row = (grp2 << 2) + rr;
                const float* trow = g_t + (size_t)row * HID;
                float vb[8]; float ls = 0.f, lq = 0.f;
                #pragma unroll
                for (int u = 0; u < 8; u++) {
                    float v = __ldcg(trow + u * 128 + lt);
                    vb[u] = v; ls += v; lq += v * v;
                }
                #pragma unroll
                for (int o = 16; o > 0; o >>= 1) {
                    ls += __shfl_down_sync(0xffffffffu, ls, o);
                    lq += __shfl_down_sync(0xffffffffu, lq, o);
                }
                if (lane == 0) { redA[g * 4 + w4] = ls; redB[g * 4 + w4] = lq; }
                __syncthreads();
                float S = redA[g * 4] + redA[g * 4 + 1] + redA[g * 4 + 2] + redA[g * 4 + 3];
                float Q = redB[g * 4] + redB[g * 4 + 1] + redB[g * 4 + 2] + redB[g * 4 + 3];
                float mu = S * (1.f / 1024.f);
                float rstd = rsqrtf(Q * (1.f / 1024.f) - mu * mu + 1e-5f);
                #pragma unroll
                for (int u = 0; u < 8; u++) {
                    int i = u * 128 + lt;
                    float v = (vb[u] - mu) * rstd * __ldg(pln_w + i) + __ldg(pln_b + i);
                    pf[rr * 1024 + i] = v * normcdff(v);
                }
                __syncthreads();
            }
            {
                float a0 = 0.f, a1 = 0.f, a2 = 0.f, a3 = 0.f;
                const int kq0 = g * 128;
                #pragma unroll 2
                for (int kq = 0; kq < 128; kq++) {
                    float4 wv = g_p2q[(size_t)(kq0 + kq) * 128 + lt];
                    float4 g0 = *(const float4*)(pf + 0 * 1024 + (kq0 + kq) * 4);
                    float4 g1 = *(const float4*)(pf + 1 * 1024 + (kq0 + kq) * 4);
                    float4 g2 = *(const float4*)(pf + 2 * 1024 + (kq0 + kq) * 4);
                    float4 g3 = *(const float4*)(pf + 3 * 1024 + (kq0 + kq) * 4);
                    a0 += g0.x * wv.x + g0.y * wv.y + g0.z * wv.z + g0.w * wv.w;
                    a1 += g1.x * wv.x + g1.y * wv.y + g1.z * wv.z + g1.w * wv.w;
                    a2 += g2.x * wv.x + g2.y * wv.y + g2.z * wv.z + g2.w * wv.w;
                    a3 += g3.x * wv.x + g3.y * wv.y + g3.z * wv.z + g3.w * wv.w;
                }
                psum[(0 * 2 + g) * 128 + lt] = a0;
                psum[(1 * 2 + g) * 128 + lt] = a1;
                psum[(2 * 2 + g) * 128 + lt] = a2;
                psum[(3 * 2 + g) * 128 + lt] = a3;
            }
            __syncthreads();
            for (int idx = tid; idx < 512; idx += NTHREADS) {
                int r = idx >> 7, o = idx & 127;
                int row = (grp2 << 2) + r;
                float y = psum[(r * 2) * 128 + o] + psum[(r * 2 + 1) * 128 + o] + __ldg(p2_b + o);
                g_xp[pk_off(row, o)] = __float2half_rn(y);
                out[(size_t)row * SEQL * NOUT + s * NOUT + o] = y;
            }
            __syncthreads();
        }
        garrive(grp, slot, gep);
    }
}

// ---------------- launch ----------------
extern "C" void kernel_launch(void* const* d_in, const int* in_sizes, int n_in,
                              void* d_out, int out_size) {
    (void)in_sizes; (void)n_in; (void)out_size;
    cudaFuncSetAttribute(dec_kernel, cudaFuncAttributeMaxDynamicSharedMemorySize, SMEM_BYTES);

    const float* z      = (const float*)d_in[0];
    const float* lin1_w = (const float*)d_in[1];
    const float* lin1_b = (const float*)d_in[2];
    const float* ln1_w  = (const float*)d_in[3];
    const float* ln1_b  = (const float*)d_in[4];
    const float* w_ih0  = (const float*)d_in[5];
    const float* w_hh0  = (const float*)d_in[6];
    const float* b0     = (const float*)d_in[7];
    const float* w_ih1  = (const float*)d_in[8];
    const float* w_hh1  = (const float*)d_in[9];
    const float* b1     = (const float*)d_in[10];
    const float* p1_w   = (const float*)d_in[11];
    const float* p1_b   = (const float*)d_in[12];
    const float* pln_w  = (const float*)d_in[13];
    const float* pln_b  = (const float*)d_in[14];
    const float* p2_w   = (const float*)d_in[15];
    const float* p2_b   = (const float*)d_in[16];

    dec_kernel<<<NBLOCKS, NTHREADS, SMEM_BYTES>>>(
        z, lin1_w, lin1_b, ln1_w, ln1_b,
        w_ih0, w_hh0, b0, w_ih1, w_hh1, b1,
        p1_w, p1_b, pln_w, pln_b, p2_w, p2_b,
        (float*)d_out);
}

// round 15
// speedup vs baseline: 1.3393x; 1.1081x over previous
#include <cuda_runtime.h>
#include <cuda_fp16.h>
#include <mma.h>
#include <math.h>
#include <stdint.h>

using namespace nvcuda;
using fp16 = __half;

#define LATENT 256
#define HID    1024
#define NOUT   128
#define SEQL   96

#define NTHREADS 256
#define NBLOCKS  128
#define LDA    136           // padded leading dim for 128-wide K chunks (272B rows)
#define ABLK   17408         // elems per 128x136 block
#define ABLKB  34816         // bytes per 128x136 fp16 block
#define NSTAGE 3
#define STGMAX 69632         // bytes per stage (A + B at NFW=4)

// smem: 1024 align slack + 1024 hdr (mbars) + 3 stage buffers = 210944
#define SMEM_BYTES (1024 + 1024 + NSTAGE * STGMAX)

// ---------------- device scratch (packed layouts, 128-wide K chunks) ----------------
__device__ __align__(16) fp16 g_lin1p[32 * 2 * (64 * 136)];    // BN=64, K=256 (2 chunks)
__device__ __align__(16) fp16 g_wih0p[32 * 1 * (128 * 136)];   // BN=128 gated, K=128 (1 chunk)
__device__ __align__(16) fp16 g_whh0p[32 * 8 * (128 * 136)];   // BN=128 gated, K=1024 (8 chunks)
__device__ __align__(16) fp16 g_wih1p[32 * 8 * (128 * 136)];
__device__ __align__(16) fp16 g_whh1p[32 * 8 * (128 * 136)];
__device__ __align__(16) fp16 g_p1p[32 * 8 * (32 * 136)];      // BN=32, K=1024
__device__ __align__(16) float4 g_p2q[256 * 128];              // p2_w transposed k-quad major
// activations: single fp16 plane, packed [kchunk][mgroup][128 x 136]
__device__ __align__(16) fp16 g_zp[2 * 4 * 17408];
__device__ __align__(16) fp16 g_xp[1 * 4 * 17408];
__device__ __align__(16) fp16 g_h1p[2][8 * 4 * 17408];         // [pingpong]
__device__ __align__(16) fp16 g_h2p[2][8 * 4 * 17408];
__device__ float g_c1[2][512 * HID];
__device__ float g_c2[2][512 * HID];
__device__ float g_u[512 * 2 * HID];
__device__ float g_t[512 * HID];
// barriers
__device__ volatile unsigned g_arrive[256];
__device__ volatile unsigned g_release;
__device__ __align__(128) volatile unsigned g_flag[4][32];

typedef wmma::fragment<wmma::accumulator, 16, 16, 16, float> CFrag;
typedef wmma::fragment<wmma::matrix_a, 16, 16, 16, fp16, wmma::row_major> AFrag;
typedef wmma::fragment<wmma::matrix_b, 16, 16, 16, fp16, wmma::col_major> BFrag;

// ---------------- PTX helpers ----------------
__device__ __forceinline__ uint32_t smem_u32(const void* p) {
    uint32_t a;
    asm("{ .reg .u64 t; cvta.to.shared.u64 t, %1; cvt.u32.u64 %0, t; }" : "=r"(a) : "l"(p));
    return a;
}
#define MBAR_INIT(a, c) \
    asm volatile("mbarrier.init.shared.b64 [%0], %1;" :: "r"(a), "r"((uint32_t)(c)) : "memory")
#define MBAR_EXPECT(a, n) \
    asm volatile("mbarrier.arrive.expect_tx.shared.b64 _, [%0], %1;" :: "r"(a), "r"((uint32_t)(n)) : "memory")
#define MBAR_ARRIVE(a) \
    asm volatile("mbarrier.arrive.shared.b64 _, [%0];" :: "r"((uint32_t)(a)) : "memory")
#define MBAR_WAIT(a, par) do { \
    uint32_t _m = (a), _p = (par), _d; \
    asm volatile("{\n\t.reg .pred p;\n\t" \
        "mbarrier.try_wait.parity.acquire.cta.shared::cta.b64 p, [%1], %2;\n\t" \
        "selp.b32 %0, 1, 0, p;\n\t}" : "=r"(_d) : "r"(_m), "r"(_p) : "memory"); \
    if (!_d) { \
        asm volatile("{\n\t.reg .pred P1;\n\tWL_%=:\n\t" \
            "mbarrier.try_wait.parity.acquire.cta.shared::cta.b64 P1, [%0], %1, 0x989680;\n\t" \
            "@P1 bra.uni WD_%=;\n\tbra.uni WL_%=;\n\tWD_%=:\n\t}" \
            :: "r"(_m), "r"(_p) : "memory"); \
    } } while (0)
#define BULK_G2S(dst, src, sz, mbar) \
    asm volatile("cp.async.bulk.shared::cluster.global.mbarrier::complete_tx::bytes [%0], [%1], %2, [%3];" \
        :: "r"((uint32_t)(dst)), "l"(src), "r"((uint32_t)(sz)), "r"((uint32_t)(mbar)) : "memory")

// ---------------- global barrier (S0 only) ----------------
__device__ __forceinline__ void gridbar(unsigned& epoch) {
    epoch++;
    __threadfence();
    __syncthreads();
    if (blockIdx.x == 0) {
        if (threadIdx.x == 0) g_arrive[0] = epoch;
        for (int b = threadIdx.x; b < (int)gridDim.x; b += blockDim.x) {
            while (g_arrive[b] < epoch) { __nanosleep(16); }
        }
        __syncthreads();
        if (threadIdx.x == 0) { __threadfence(); g_release = epoch; }
    } else {
        if (threadIdx.x == 0) {
            g_arrive[blockIdx.x] = epoch;
            while (g_release < epoch) { __nanosleep(16); }
        }
    }
    __syncthreads();
}

// ---------------- group barrier (32 blocks sharing mg), split arrive/wait ----------------
__device__ __forceinline__ void garrive(int grp, int slot, unsigned& ep) {
    __threadfence();
    __syncthreads();
    ep++;
    if (threadIdx.x == 0) g_flag[grp][slot] = ep;
}
__device__ __forceinline__ void gwait(int grp, unsigned ep) {
    if (threadIdx.x < 32) {
        while (g_flag[grp][threadIdx.x] < ep) { __nanosleep(16); }
        __threadfence();
    }
    __syncthreads();
}

// fast activations (~1e-6 rel err)
__device__ __forceinline__ float sigm(float x) {
    return __fdividef(1.f, 1.f + __expf(-x));
}
__device__ __forceinline__ float tanh_f(float x) {
    float e = __expf(2.f * x);
    return 1.f - __fdividef(2.f, e + 1.f);
}

// pack activation offset: (row 0..511, col) -> packed elem index (128-wide K chunks)
__device__ __forceinline__ size_t pk_off(int row, int col) {
    return ((size_t)((col >> 7) * 4 + (row >> 7))) * ABLK + (size_t)(row & 127) * LDA + (col & 127);
}

// ---------------- S0 weight packer (single fp16 plane, 128-wide chunks) ----------------
__device__ void pack_w(const float* __restrict__ W, fp16* __restrict__ dst,
                       int K, int BN, int ntiles, int gated, int gt, int gs)
{
    const int nch = K >> 7;
    const int tot = ntiles * nch * BN * 32;   // float4 units (32 per 128-wide row)
    for (int i = gt; i < tot; i += gs) {
        int k4 = i & 31;
        int rest = i >> 5;
        int n = rest % BN; rest /= BN;
        int c = rest % nch;
        int nt = rest / nch;
        int row = gated ? ((n >> 5) * HID + nt * 32 + (n & 31)) : (nt * BN + n);
        float4 v = *(const float4*)(W + (size_t)row * K + c * 128 + k4 * 4);
        fp16 h[4];
        h[0] = __float2half_rn(v.x); h[1] = __float2half_rn(v.y);
        h[2] = __float2half_rn(v.z); h[3] = __float2half_rn(v.w);
        size_t d = ((size_t)(nt * nch + c) * BN + n) * LDA + k4 * 4;
        *(uint2*)(dst + d) = *(uint2*)h;
    }
}

// ---------------- pipeline state ----------------
struct Pipe {
    int fullph[NSTAGE];
    int emptyph[NSTAGE];
    int pcnt, ccnt;
};
struct Seg { const fp16 *a, *b; int nch, astr, bstr; };

// ---------------- 3-stage mbar-pipelined wmma GEMM (fp16, K-chunk 128) ----------------
// 8 warps: wm = warp>>1 (4 row groups of 32), wn = warp&1 (2 col groups of 16*NFW).
template <int NFW>
__device__ void gemm_pk(CFrag (&acc)[2][NFW], char* P, uint32_t pbase,
                        const Seg* segs, int nseg, Pipe& pp)
{
    constexpr int BB = 32 * NFW * 272;                // B plane bytes (BN rows x 272B)
    constexpr uint32_t TX = ABLKB + BB;
    const int tid = threadIdx.x;
    const int warp = tid >> 5, lane = tid & 31;
    const int wm = warp >> 1, wn = warp & 1;

    int nt = 0;
    for (int s = 0; s < nseg; s++) nt += segs[s].nch;

    auto do_fill = [&](int gidx) {
        int c = gidx, si = 0;
        while (c >= segs[si].nch) { c -= segs[si].nch; si++; }
        const Seg& S = segs[si];
        int st = pp.pcnt % NSTAGE;
        if (tid == 0) {
            MBAR_WAIT(pbase + 64 + (st << 3), (uint32_t)(pp.emptyph[st] & 1));
            uint32_t d = pbase + 1024 + st * STGMAX;
            uint32_t mb = pbase + (st << 3);
            MBAR_EXPECT(mb, TX);
            BULK_G2S(d,         (const char*)(S.a + (size_t)c * S.astr), ABLKB, mb);
            BULK_G2S(d + ABLKB, (const char*)(S.b + (size_t)c * S.bstr), BB, mb);
        }
        pp.emptyph[st]++;
        pp.pcnt++;
    };

    const int pre = nt < 2 ? nt : 2;
    for (int g = 0; g < pre; g++) do_fill(g);

    for (int i = 0; i < nt; i++) {
        if (i + 2 < nt) do_fill(i + 2);
        const int st = pp.ccnt % NSTAGE;
        MBAR_WAIT(pbase + (st << 3), (uint32_t)(pp.fullph[st] & 1));
        pp.fullph[st]++;
        pp.ccnt++;

        const fp16* sA = (const fp16*)(P + 1024 + st * STGMAX);
        const fp16* sB = sA + ABLK;
        #pragma unroll
        for (int kk = 0; kk < 8; kk++) {
            AFrag a0, a1;
            wmma::load_matrix_sync(a0, sA + (wm * 32 + 0)  * LDA + kk * 16, LDA);
            wmma::load_matrix_sync(a1, sA + (wm * 32 + 16) * LDA + kk * 16, LDA);
            BFrag bf[NFW];
            #pragma unroll
            for (int nf = 0; nf < NFW; nf++)
                wmma::load_matrix_sync(bf[nf], sB + (wn * (16 * NFW) + nf * 16) * LDA + kk * 16, LDA);
            #pragma unroll
            for (int nf = 0; nf < NFW; nf++) {
                wmma::mma_sync(acc[0][nf], a0, bf[nf], acc[0][nf]);
                wmma::mma_sync(acc[1][nf], a1, bf[nf], acc[1][nf]);
            }
        }
        if (lane == 0) MBAR_ARRIVE(pbase + 64 + (st << 3));
    }
}

// ---------------- epilogues (syncthreads at entry: patch aliases stage smem) ----------------
__device__ void lstm_epi(CFrag (&acc)[2][4], char* P, const float* __restrict__ bias,
                         const float* __restrict__ c_in, float* __restrict__ c_out,
                         fp16* __restrict__ hp,
                         int mbase, int jbase)
{
    __syncthreads();
    float* pf = (float*)(P + 1024);       // patch [128][132]
    const int tid = threadIdx.x, warp = tid >> 5;
    const int wm = warp >> 1, wn = warp & 1;
    #pragma unroll
    for (int i = 0; i < 2; i++)
        #pragma unroll
        for (int nf = 0; nf < 4; nf++)
            wmma::store_matrix_sync(pf + (wm * 32 + i * 16) * 132 + wn * 64 + nf * 16,
                                    acc[i][nf], 132, wmma::mem_row_major);
    __syncthreads();
    #pragma unroll 4
    for (int e = tid; e < 128 * 32; e += NTHREADS) {
        int r = e >> 5, j = e & 31;
        int row = mbase + r, col = jbase + j;
        float iv = pf[r * 132 + j]      + __ldg(bias + col);
        float fv = pf[r * 132 + 32 + j] + __ldg(bias + HID + col);
        float gv = pf[r * 132 + 64 + j] + __ldg(bias + 2 * HID + col);
        float ov = pf[r * 132 + 96 + j] + __ldg(bias + 3 * HID + col);
        float cold = __ldcg(c_in + (size_t)row * HID + col);
        float cn = sigm(fv) * cold + sigm(iv) * tanh_f(gv);
        float hn = sigm(ov) * tanh_f(cn);
        c_out[(size_t)row * HID + col] = cn;
        hp[pk_off(row, col)] = __float2half_rn(hn);
    }
    __syncthreads();
}

template <int NFW>
__device__ void store_epi(CFrag (&acc)[2][NFW], char* P, const float* __restrict__ bias,
                          float* __restrict__ dst, int stride, int mbase, int nbase)
{
    __syncthreads();
    constexpr int BN = 32 * NFW, PS = BN + 4;
    float* pf = (float*)(P + 1024);
    const int tid = threadIdx.x, warp = tid >> 5;
    const int wm = warp >> 1, wn = warp & 1;
    #pragma unroll
    for (int i = 0; i < 2; i++)
        #pragma unroll
        for (int nf = 0; nf < NFW; nf++)
            wmma::store_matrix_sync(pf + (wm * 32 + i * 16) * PS + wn * (16 * NFW) + nf * 16,
                                    acc[i][nf], PS, wmma::mem_row_major);
    __syncthreads();
    for (int e = tid; e < 128 * BN; e += NTHREADS) {
        int r = e / BN, c = e % BN;
        dst[(size_t)(mbase + r) * stride + nbase + c] = pf[r * PS + c] + __ldg(bias + nbase + c);
    }
    __syncthreads();
}

// ---------------- the persistent decoder kernel ----------------
__global__ void __launch_bounds__(NTHREADS, 1) dec_kernel(
    const float* __restrict__ z,     const float* __restrict__ lin1_w, const float* __restrict__ lin1_b,
    const float* __restrict__ ln1_w, const float* __restrict__ ln1_b,
    const float* __restrict__ w_ih0, const float* __restrict__ w_hh0,  const float* __restrict__ b0,
    const float* __restrict__ w_ih1, const float* __restrict__ w_hh1,  const float* __restrict__ b1,
    const float* __restrict__ p1_w,  const float* __restrict__ p1_b,
    const float* __restrict__ pln_w, const float* __restrict__ pln_b,
    const float* __restrict__ p2_w,  const float* __restrict__ p2_b,
    float* __restrict__ out)
{
    extern __shared__ char pool[];
    __shared__ float redA[8], redB[8];
    const int bid = blockIdx.x, nb = gridDim.x, tid = threadIdx.x;
    const int lane = tid & 31;
    const int grp = bid >> 5, slot = bid & 31;
    uint32_t raw = smem_u32(pool);
    uint32_t pbase = (raw + 1023) & ~1023u;
    char* P = pool + (pbase - raw);
    unsigned epoch = g_release;
    unsigned gep = g_flag[grp][slot];
    Pipe pp;
    #pragma unroll
    for (int s = 0; s < NSTAGE; s++) { pp.fullph[s] = 0; pp.emptyph[s] = 0; }
    pp.pcnt = 0; pp.ccnt = 0;

    if (tid == 0) {
        #pragma unroll
        for (int s = 0; s < NSTAGE; s++) {
            MBAR_INIT(pbase + (s << 3), 1);       // full: tx-based
            MBAR_INIT(pbase + 64 + (s << 3), 8);  // empty: one arrive per warp
        }
    }
    __syncthreads();
    if (lane == 0) {
        #pragma unroll
        for (int s = 0; s < NSTAGE; s++) MBAR_ARRIVE(pbase + 64 + (s << 3));
    }
    __syncthreads();

    // ---- S0: pack weights (fp16, 128-chunks); pack z; transpose p2; zero x
    {
        int gt = bid * NTHREADS + tid, gs = nb * NTHREADS;
        pack_w(lin1_w, g_lin1p, LATENT, 64, 32, 0, gt, gs);
        pack_w(w_ih0,  g_wih0p, NOUT, 128, 32, 1, gt, gs);
        pack_w(w_hh0,  g_whh0p, HID, 128, 32, 1, gt, gs);
        pack_w(w_ih1,  g_wih1p, HID, 128, 32, 1, gt, gs);
        pack_w(w_hh1,  g_whh1p, HID, 128, 32, 1, gt, gs);
        pack_w(p1_w,   g_p1p,   HID, 32, 32, 0, gt, gs);
        // z: 2 chunks x 4 mg x 128 rows x 32 k4
        for (int i = gt; i < 2 * 4 * 128 * 32; i += gs) {
            int k4 = i & 31, r = (i >> 5) & 127, mg = (i >> 12) & 3, c = i >> 14;
            float4 v = *(const float4*)(z + (size_t)(mg * 128 + r) * LATENT + c * 128 + k4 * 4);
            fp16 h[4];
            h[0] = __float2half_rn(v.x); h[1] = __float2half_rn(v.y);
            h[2] = __float2half_rn(v.z); h[3] = __float2half_rn(v.w);
            size_t d = (size_t)(c * 4 + mg) * ABLK + (size_t)r * LDA + k4 * 4;
            *(uint2*)(g_zp + d) = *(uint2*)h;
        }
        for (int i = gt; i < 256 * 128; i += gs) {
            int o = i & 127, kq = i >> 7;
            g_p2q[i] = *(const float4*)(p2_w + (size_t)o * HID + kq * 4);
        }
        for (int i = gt; i < 4 * ABLK; i += gs) {
            g_xp[i] = __float2half_rn(0.f);
        }
    }
    gridbar(epoch);

    // ---- S1: u = z @ lin1_w^T + lin1_b  (512 x 2048): 128 tiles of 128x64
    {
        int mg = grp, nt = slot;
        CFrag acc[2][2];
        #pragma unroll
        for (int i = 0; i < 2; i++) { wmma::fill_fragment(acc[i][0], 0.f); wmma::fill_fragment(acc[i][1], 0.f); }
        Seg sg[1] = {{g_zp + (size_t)mg * ABLK,
                      g_lin1p + (size_t)nt * 2 * (64 * 136),
                      2, 4 * ABLK, 64 * 136}};
        gemm_pk<2>(acc, P, pbase, sg, 1, pp);
        store_epi<2>(acc, P, lin1_b, g_u, 2 * HID, mg << 7, nt << 6);
    }
    garrive(grp, slot, gep); gwait(grp, gep);

    // ---- S2: LayerNorm(2048) + gelu -> h0/c0 (both cells)
    {
        float* pf = (float*)(P + 1024);
        const int g = tid >> 7, lt = tid & 127, w4 = (tid >> 5) & 3;
        {
            int grp2 = bid;
            for (int pass = 0; pass < 2; pass++) {
                int row = (grp2 << 2) + pass * 2 + g;
                const float* urow = g_u + (size_t)row * 2 * HID;
                float ls = 0.f, lq = 0.f;
                #pragma unroll
                for (int u = 0; u < 16; u++) {
                    float v = __ldcg(urow + u * 128 + lt);
                    pf[g * 2048 + u * 128 + lt] = v;
                    ls += v; lq += v * v;
                }
                #pragma unroll
                for (int o = 16; o > 0; o >>= 1) {
                    ls += __shfl_down_sync(0xffffffffu, ls, o);
                    lq += __shfl_down_sync(0xffffffffu, lq, o);
                }
                if (lane == 0) { redA[g * 4 + w4] = ls; redB[g * 4 + w4] = lq; }
                __syncthreads();
                float S = redA[g * 4] + redA[g * 4 + 1] + redA[g * 4 + 2] + redA[g * 4 + 3];
                float Q = redB[g * 4] + redB[g * 4 + 1] + redB[g * 4 + 2] + redB[g * 4 + 3];
                float mu = S * (1.f / 2048.f);
                float rstd = rsqrtf(Q * (1.f / 2048.f) - mu * mu + 1e-5f);
                #pragma unroll
                for (int u = 0; u < 16; u++) {
                    int i = u * 128 + lt;
                    float v = (pf[g * 2048 + i] - mu) * rstd * __ldg(ln1_w + i) + __ldg(ln1_b + i);
                    float ge = v * normcdff(v);
                    if (i < HID) {
                        fp16 hv = __float2half_rn(ge);
                        size_t off = pk_off(row, i);
                        g_h1p[0][off] = hv;
                        g_h2p[0][off] = hv;
                    } else {
                        g_c1[0][(size_t)row * HID + i - HID] = ge;
                        g_c2[0][(size_t)row * HID + i - HID] = ge;
                    }
                }
                __syncthreads();
            }
        }
    }
    garrive(grp, slot, gep); gwait(grp, gep);

    // ---- main sequential loop (split group barriers; hidden waits)
    for (int s = 0; s < SEQL; s++) {
        const int pi = s & 1, po = pi ^ 1;
        const int mg = grp, ntl = slot;

        // P1: seg_h (8 chunks, no dep on P4) -> wait x -> seg_x (1 chunk) -> epilogue -> arrive
        {
            CFrag acc[2][4];
            #pragma unroll
            for (int i = 0; i < 2; i++)
                #pragma unroll
                for (int j = 0; j < 4; j++) wmma::fill_fragment(acc[i][j], 0.f);
            Seg sgh[1] = {{g_h1p[pi] + (size_t)mg * ABLK,
                           g_whh0p + (size_t)ntl * 8 * (128 * 136),
                           8, 4 * ABLK, 128 * 136}};
            gemm_pk<4>(acc, P, pbase, sgh, 1, pp);
            gwait(grp, gep);                    // x from P4(s-1) ready (no-op at s=0)
            Seg sgx[1] = {{g_xp + (size_t)mg * ABLK,
                           g_wih0p + (size_t)ntl * 1 * (128 * 136),
                           1, 4 * ABLK, 128 * 136}};
            gemm_pk<4>(acc, P, pbase, sgx, 1, pp);
            lstm_epi(acc, P, b0, g_c1[pi], g_c1[po], g_h1p[po], mg << 7, ntl << 5);
        }
        garrive(grp, slot, gep);

        // P2: seg_h2 (8 chunks, no dep on P1) -> wait h1 -> seg_h1 (8 chunks) -> epilogue -> arrive
        {
            CFrag acc[2][4];
            #pragma unroll
            for (int i = 0; i < 2; i++)
                #pragma unroll
                for (int j = 0; j < 4; j++) wmma::fill_fragment(acc[i][j], 0.f);
            Seg sg2[1] = {{g_h2p[pi] + (size_t)mg * ABLK,
                           g_whh1p + (size_t)ntl * 8 * (128 * 136),
                           8, 4 * ABLK, 128 * 136}};
            gemm_pk<4>(acc, P, pbase, sg2, 1, pp);
            gwait(grp, gep);                    // h1_new ready
            Seg sg1[1] = {{g_h1p[po] + (size_t)mg * ABLK,
                           g_wih1p + (size_t)ntl * 8 * (128 * 136),
                           8, 4 * ABLK, 128 * 136}};
            gemm_pk<4>(acc, P, pbase, sg1, 1, pp);
            lstm_epi(acc, P, b1, g_c2[pi], g_c2[po], g_h2p[po], mg << 7, ntl << 5);
        }
        garrive(grp, slot, gep);

        // P3: wait h2 -> t = h2_new @ p1_w^T + p1_b (8 chunks) -> arrive
        gwait(grp, gep);
        {
            CFrag acc[2][1];
            wmma::fill_fragment(acc[0][0], 0.f);
            wmma::fill_fragment(acc[1][0], 0.f);
            Seg sg[1] = {{g_h2p[po] + (size_t)mg * ABLK,
                          g_p1p + (size_t)ntl * 8 * (32 * 136),
                          8, 4 * ABLK, 32 * 136}};
            gemm_pk<1>(acc, P, pbase, sg, 1, pp);
            store_epi<1>(acc, P, p1_b, g_t, HID, mg << 7, ntl << 5);
        }
        garrive(grp, slot, gep);

        // P4: wait t -> LayerNorm + gelu + GEMV -> x, out -> arrive
        gwait(grp, gep);
        {
            float* pf = (float*)(P + 1024);
            float* psum = pf + 4096;
            const int g = tid >> 7, lt = tid & 127, w4 = (tid >> 5) & 3;
            const int grp2 = bid;
            for (int pass = 0; pass < 2; pass++) {
                int rr = pass * 2 + g;
                int row = (grp2 << 2) + rr;
                const float* trow = g_t + (size_t)row * HID;
                float vb[8]; float ls = 0.f, lq = 0.f;
                #pragma unroll
                for (int u = 0; u < 8; u++) {
                    float v = __ldcg(trow + u * 128 + lt);
                    vb[u] = v; ls += v; lq += v * v;
                }
                #pragma unroll
                for (int o = 16; o > 0; o >>= 1) {
                    ls += __shfl_down_sync(0xffffffffu, ls, o);
                    lq += __shfl_down_sync(0xffffffffu, lq, o);
                }
                if (lane == 0) { redA[g * 4 + w4] = ls; redB[g * 4 + w4] = lq; }
                __syncthreads();
                float S = redA[g * 4] + redA[g * 4 + 1] + redA[g * 4 + 2] + redA[g * 4 + 3];
                float Q = redB[g * 4] + redB[g * 4 + 1] + redB[g * 4 + 2] + redB[g * 4 + 3];
                float mu = S * (1.f / 1024.f);
                float rstd = rsqrtf(Q * (1.f / 1024.f) - mu * mu + 1e-5f);
                #pragma unroll
                for (int u = 0; u < 8; u++) {
                    int i = u * 128 + lt;
                    float v = (vb[u] - mu) * rstd * __ldg(pln_w + i) + __ldg(pln_b + i);
                    pf[rr * 1024 + i] = v * normcdff(v);
                }
                __syncthreads();
            }
            {
                float a0 = 0.f, a1 = 0.f, a2 = 0.f, a3 = 0.f;
                const int kq0 = g * 128;
                #pragma unroll 2
                for (int kq = 0; kq < 128; kq++) {
                    float4 wv = g_p2q[(size_t)(kq0 + kq) * 128 + lt];
                    float4 g0 = *(const float4*)(pf + 0 * 1024 + (kq0 + kq) * 4);
                    float4 g1 = *(const float4*)(pf + 1 * 1024 + (kq0 + kq) * 4);
                    float4 g2 = *(const float4*)(pf + 2 * 1024 + (kq0 + kq) * 4);
                    float4 g3 = *(const float4*)(pf + 3 * 1024 + (kq0 + kq) * 4);
                    a0 += g0.x * wv.x + g0.y * wv.y + g0.z * wv.z + g0.w * wv.w;
                    a1 += g1.x * wv.x + g1.y * wv.y + g1.z * wv.z + g1.w * wv.w;
                    a2 += g2.x * wv.x + g2.y * wv.y + g2.z * wv.z + g2.w * wv.w;
                    a3 += g3.x * wv.x + g3.y * wv.y + g3.z * wv.z + g3.w * wv.w;
                }
                psum[(0 * 2 + g) * 128 + lt] = a0;
                psum[(1 * 2 + g) * 128 + lt] = a1;
                psum[(2 * 2 + g) * 128 + lt] = a2;
                psum[(3 * 2 + g) * 128 + lt] = a3;
            }
            __syncthreads();
            for (int idx = tid; idx < 512; idx += NTHREADS) {
                int r = idx >> 7, o = idx & 127;
                int row = (grp2 << 2) + r;
                float y = psum[(r * 2) * 128 + o] + psum[(r * 2 + 1) * 128 + o] + __ldg(p2_b + o);
                g_xp[pk_off(row, o)] = __float2half_rn(y);
                out[(size_t)row * SEQL * NOUT + s * NOUT + o] = y;
            }
            __syncthreads();
        }
        garrive(grp, slot, gep);
    }
}

// ---------------- launch ----------------
extern "C" void kernel_launch(void* const* d_in, const int* in_sizes, int n_in,
                              void* d_out, int out_size) {
    (void)in_sizes; (void)n_in; (void)out_size;
    cudaFuncSetAttribute(dec_kernel, cudaFuncAttributeMaxDynamicSharedMemorySize, SMEM_BYTES);

    const float* z      = (const float*)d_in[0];
    const float* lin1_w = (const float*)d_in[1];
    const float* lin1_b = (const float*)d_in[2];
    const float* ln1_w  = (const float*)d_in[3];
    const float* ln1_b  = (const float*)d_in[4];
    const float* w_ih0  = (const float*)d_in[5];
    const float* w_hh0  = (const float*)d_in[6];
    const float* b0     = (const float*)d_in[7];
    const float* w_ih1  = (const float*)d_in[8];
    const float* w_hh1  = (const float*)d_in[9];
    const float* b1     = (const float*)d_in[10];
    const float* p1_w   = (const float*)d_in[11];
    const float* p1_b   = (const float*)d_in[12];
    const float* pln_w  = (const float*)d_in[13];
    const float* pln_b  = (const float*)d_in[14];
    const float* p2_w   = (const float*)d_in[15];
    const float* p2_b   = (const float*)d_in[16];

    dec_kernel<<<NBLOCKS, NTHREADS, SMEM_BYTES>>>(
        z, lin1_w, lin1_b, ln1_w, ln1_b,
        w_ih0, w_hh0, b0, w_ih1, w_hh1, b1,
        p1_w, p1_b, pln_w, pln_b, p2_w, p2_b,
        (float*)d_out);
}

// round 16
// speedup vs baseline: 1.4548x; 1.0863x over previous
#include <cuda_runtime.h>
#include <cuda_fp16.h>
#include <mma.h>
#include <math.h>
#include <stdint.h>

using namespace nvcuda;
using fp16 = __half;

#define LATENT 256
#define HID    1024
#define NOUT   128
#define SEQL   96

#define NTHREADS 256
#define NBLOCKS  128
#define LDA    136           // padded leading dim for 128-wide K chunks (272B rows)
#define ABLK   17408         // elems per 128x136 block
#define ABLKB  34816         // bytes per 128x136 fp16 block
#define NSTAGE 3
#define STGMAX 69632         // bytes per stage (A + B at NFW=4)

// smem: 1024 align slack + 1024 hdr (mbars) + 3 stage buffers = 210944
#define SMEM_BYTES (1024 + 1024 + NSTAGE * STGMAX)

// ---------------- device scratch (packed layouts, 128-wide K chunks) ----------------
__device__ __align__(16) fp16 g_lin1p[32 * 2 * (64 * 136)];    // BN=64, K=256 (2 chunks)
__device__ __align__(16) fp16 g_wih0p[32 * 1 * (128 * 136)];   // BN=128 gated, K=128 (1 chunk)
__device__ __align__(16) fp16 g_whh0p[32 * 8 * (128 * 136)];   // BN=128 gated, K=1024 (8 chunks)
__device__ __align__(16) fp16 g_wih1p[32 * 8 * (128 * 136)];
__device__ __align__(16) fp16 g_whh1p[32 * 8 * (128 * 136)];
__device__ __align__(16) fp16 g_p1p[32 * 8 * (32 * 136)];      // BN=32, K=1024
__device__ __align__(16) float4 g_p2q[256 * 128];              // p2_w transposed k-quad major
// activations: single fp16 plane, packed [kchunk][mgroup][128 x 136]
__device__ __align__(16) fp16 g_zp[2 * 4 * 17408];
__device__ __align__(16) fp16 g_xp[1 * 4 * 17408];
__device__ __align__(16) fp16 g_h1p[2][8 * 4 * 17408];         // [pingpong]
__device__ __align__(16) fp16 g_h2p[2][8 * 4 * 17408];
__device__ float g_c1[2][512 * HID];
__device__ float g_c2[2][512 * HID];
__device__ float g_u[512 * 2 * HID];
__device__ float g_t[512 * HID];
// barriers
__device__ volatile unsigned g_arrive[256];
__device__ volatile unsigned g_release;
__device__ __align__(128) volatile unsigned g_flag[4][32];

typedef wmma::fragment<wmma::accumulator, 16, 16, 16, float> CFrag;
typedef wmma::fragment<wmma::matrix_a, 16, 16, 16, fp16, wmma::row_major> AFrag;
typedef wmma::fragment<wmma::matrix_b, 16, 16, 16, fp16, wmma::col_major> BFrag;

// ---------------- PTX helpers ----------------
__device__ __forceinline__ uint32_t smem_u32(const void* p) {
    uint32_t a;
    asm("{ .reg .u64 t; cvta.to.shared.u64 t, %1; cvt.u32.u64 %0, t; }" : "=r"(a) : "l"(p));
    return a;
}
#define MBAR_INIT(a, c) \
    asm volatile("mbarrier.init.shared.b64 [%0], %1;" :: "r"(a), "r"((uint32_t)(c)) : "memory")
#define MBAR_EXPECT(a, n) \
    asm volatile("mbarrier.arrive.expect_tx.shared.b64 _, [%0], %1;" :: "r"(a), "r"((uint32_t)(n)) : "memory")
#define MBAR_ARRIVE(a) \
    asm volatile("mbarrier.arrive.shared.b64 _, [%0];" :: "r"((uint32_t)(a)) : "memory")
#define MBAR_WAIT(a, par) do { \
    uint32_t _m = (a), _p = (par), _d; \
    asm volatile("{\n\t.reg .pred p;\n\t" \
        "mbarrier.try_wait.parity.acquire.cta.shared::cta.b64 p, [%1], %2;\n\t" \
        "selp.b32 %0, 1, 0, p;\n\t}" : "=r"(_d) : "r"(_m), "r"(_p) : "memory"); \
    if (!_d) { \
        asm volatile("{\n\t.reg .pred P1;\n\tWL_%=:\n\t" \
            "mbarrier.try_wait.parity.acquire.cta.shared::cta.b64 P1, [%0], %1, 0x989680;\n\t" \
            "@P1 bra.uni WD_%=;\n\tbra.uni WL_%=;\n\tWD_%=:\n\t}" \
            :: "r"(_m), "r"(_p) : "memory"); \
    } } while (0)
#define BULK_G2S(dst, src, sz, mbar) \
    asm volatile("cp.async.bulk.shared::cluster.global.mbarrier::complete_tx::bytes [%0], [%1], %2, [%3];" \
        :: "r"((uint32_t)(dst)), "l"(src), "r"((uint32_t)(sz)), "r"((uint32_t)(mbar)) : "memory")

// ---------------- global barrier (S0 only) ----------------
__device__ __forceinline__ void gridbar(unsigned& epoch) {
    epoch++;
    __threadfence();
    __syncthreads();
    if (blockIdx.x == 0) {
        if (threadIdx.x == 0) g_arrive[0] = epoch;
        for (int b = threadIdx.x; b < (int)gridDim.x; b += blockDim.x) {
            while (g_arrive[b] < epoch) { __nanosleep(16); }
        }
        __syncthreads();
        if (threadIdx.x == 0) { __threadfence(); g_release = epoch; }
    } else {
        if (threadIdx.x == 0) {
            g_arrive[blockIdx.x] = epoch;
            while (g_release < epoch) { __nanosleep(16); }
        }
    }
    __syncthreads();
}

// ---------------- group barrier (32 blocks sharing mg), split arrive/wait ----------------
__device__ __forceinline__ void garrive(int grp, int slot, unsigned& ep) {
    __threadfence();
    __syncthreads();
    ep++;
    if (threadIdx.x == 0) g_flag[grp][slot] = ep;
}
__device__ __forceinline__ void gwait(int grp, unsigned ep) {
    if (threadIdx.x < 32) {
        while (g_flag[grp][threadIdx.x] < ep) { __nanosleep(16); }
        __threadfence();
    }
    __syncthreads();
}

// fast activations (~1e-6 rel err)
__device__ __forceinline__ float sigm(float x) {
    return __fdividef(1.f, 1.f + __expf(-x));
}
__device__ __forceinline__ float tanh_f(float x) {
    float e = __expf(2.f * x);
    return 1.f - __fdividef(2.f, e + 1.f);
}

// pack activation offset: (row 0..511, col) -> packed elem index (128-wide K chunks)
__device__ __forceinline__ size_t pk_off(int row, int col) {
    return ((size_t)((col >> 7) * 4 + (row >> 7))) * ABLK + (size_t)(row & 127) * LDA + (col & 127);
}

// ---------------- S0 weight packer (single fp16 plane, 128-wide chunks) ----------------
__device__ void pack_w(const float* __restrict__ W, fp16* __restrict__ dst,
                       int K, int BN, int ntiles, int gated, int gt, int gs)
{
    const int nch = K >> 7;
    const int tot = ntiles * nch * BN * 32;   // float4 units (32 per 128-wide row)
    for (int i = gt; i < tot; i += gs) {
        int k4 = i & 31;
        int rest = i >> 5;
        int n = rest % BN; rest /= BN;
        int c = rest % nch;
        int nt = rest / nch;
        int row = gated ? ((n >> 5) * HID + nt * 32 + (n & 31)) : (nt * BN + n);
        float4 v = *(const float4*)(W + (size_t)row * K + c * 128 + k4 * 4);
        fp16 h[4];
        h[0] = __float2half_rn(v.x); h[1] = __float2half_rn(v.y);
        h[2] = __float2half_rn(v.z); h[3] = __float2half_rn(v.w);
        size_t d = ((size_t)(nt * nch + c) * BN + n) * LDA + k4 * 4;
        *(uint2*)(dst + d) = *(uint2*)h;
    }
}

// ---------------- pipeline state ----------------
struct Pipe {
    int fullph[NSTAGE];
    int emptyph[NSTAGE];
    int pcnt, ccnt;
};
struct Seg { const fp16 *a, *b; int nch, astr, bstr; };

// ---------------- 3-stage mbar-pipelined wmma GEMM (fp16, K-chunk 128) ----------------
template <int NFW>
__device__ void gemm_pk(CFrag (&acc)[2][NFW], char* P, uint32_t pbase,
                        const Seg* segs, int nseg, Pipe& pp)
{
    constexpr int BB = 32 * NFW * 272;                // B plane bytes (BN rows x 272B)
    constexpr uint32_t TX = ABLKB + BB;
    const int tid = threadIdx.x;
    const int warp = tid >> 5, lane = tid & 31;
    const int wm = warp >> 1, wn = warp & 1;

    int nt = 0;
    for (int s = 0; s < nseg; s++) nt += segs[s].nch;

    auto do_fill = [&](int gidx) {
        int c = gidx, si = 0;
        while (c >= segs[si].nch) { c -= segs[si].nch; si++; }
        const Seg& S = segs[si];
        int st = pp.pcnt % NSTAGE;
        if (tid == 0) {
            MBAR_WAIT(pbase + 64 + (st << 3), (uint32_t)(pp.emptyph[st] & 1));
            uint32_t d = pbase + 1024 + st * STGMAX;
            uint32_t mb = pbase + (st << 3);
            MBAR_EXPECT(mb, TX);
            BULK_G2S(d,         (const char*)(S.a + (size_t)c * S.astr), ABLKB, mb);
            BULK_G2S(d + ABLKB, (const char*)(S.b + (size_t)c * S.bstr), BB, mb);
        }
        pp.emptyph[st]++;
        pp.pcnt++;
    };

    const int pre = nt < 2 ? nt : 2;
    for (int g = 0; g < pre; g++) do_fill(g);

    for (int i = 0; i < nt; i++) {
        if (i + 2 < nt) do_fill(i + 2);
        const int st = pp.ccnt % NSTAGE;
        MBAR_WAIT(pbase + (st << 3), (uint32_t)(pp.fullph[st] & 1));
        pp.fullph[st]++;
        pp.ccnt++;

        const fp16* sA = (const fp16*)(P + 1024 + st * STGMAX);
        const fp16* sB = sA + ABLK;
        #pragma unroll
        for (int kk = 0; kk < 8; kk++) {
            AFrag a0, a1;
            wmma::load_matrix_sync(a0, sA + (wm * 32 + 0)  * LDA + kk * 16, LDA);
            wmma::load_matrix_sync(a1, sA + (wm * 32 + 16) * LDA + kk * 16, LDA);
            BFrag bf[NFW];
            #pragma unroll
            for (int nf = 0; nf < NFW; nf++)
                wmma::load_matrix_sync(bf[nf], sB + (wn * (16 * NFW) + nf * 16) * LDA + kk * 16, LDA);
            #pragma unroll
            for (int nf = 0; nf < NFW; nf++) {
                wmma::mma_sync(acc[0][nf], a0, bf[nf], acc[0][nf]);
                wmma::mma_sync(acc[1][nf], a1, bf[nf], acc[1][nf]);
            }
        }
        if (lane == 0) MBAR_ARRIVE(pbase + 64 + (st << 3));
    }
}

// ---------------- epilogues (syncthreads at entry: patch aliases stage smem) ----------------
__device__ void lstm_epi(CFrag (&acc)[2][4], char* P, const float* __restrict__ bias,
                         const float* __restrict__ c_in, float* __restrict__ c_out,
                         fp16* __restrict__ hp,
                         int mbase, int jbase)
{
    __syncthreads();
    float* pf = (float*)(P + 1024);       // patch [128][132]
    const int tid = threadIdx.x, warp = tid >> 5;
    const int wm = warp >> 1, wn = warp & 1;
    #pragma unroll
    for (int i = 0; i < 2; i++)
        #pragma unroll
        for (int nf = 0; nf < 4; nf++)
            wmma::store_matrix_sync(pf + (wm * 32 + i * 16) * 132 + wn * 64 + nf * 16,
                                    acc[i][nf], 132, wmma::mem_row_major);
    __syncthreads();
    #pragma unroll 4
    for (int e = tid; e < 128 * 32; e += NTHREADS) {
        int r = e >> 5, j = e & 31;
        int row = mbase + r, col = jbase + j;
        float iv = pf[r * 132 + j]      + __ldg(bias + col);
        float fv = pf[r * 132 + 32 + j] + __ldg(bias + HID + col);
        float gv = pf[r * 132 + 64 + j] + __ldg(bias + 2 * HID + col);
        float ov = pf[r * 132 + 96 + j] + __ldg(bias + 3 * HID + col);
        float cold = __ldcg(c_in + (size_t)row * HID + col);
        float cn = sigm(fv) * cold + sigm(iv) * tanh_f(gv);
        float hn = sigm(ov) * tanh_f(cn);
        c_out[(size_t)row * HID + col] = cn;
        hp[pk_off(row, col)] = __float2half_rn(hn);
    }
    __syncthreads();
}

template <int NFW>
__device__ void store_epi(CFrag (&acc)[2][NFW], char* P, const float* __restrict__ bias,
                          float* __restrict__ dst, int stride, int mbase, int nbase)
{
    __syncthreads();
    constexpr int BN = 32 * NFW, PS = BN + 4;
    float* pf = (float*)(P + 1024);
    const int tid = threadIdx.x, warp = tid >> 5;
    const int wm = warp >> 1, wn = warp & 1;
    #pragma unroll
    for (int i = 0; i < 2; i++)
        #pragma unroll
        for (int nf = 0; nf < NFW; nf++)
            wmma::store_matrix_sync(pf + (wm * 32 + i * 16) * PS + wn * (16 * NFW) + nf * 16,
                                    acc[i][nf], PS, wmma::mem_row_major);
    __syncthreads();
    for (int e = tid; e < 128 * BN; e += NTHREADS) {
        int r = e / BN, c = e % BN;
        dst[(size_t)(mbase + r) * stride + nbase + c] = pf[r * PS + c] + __ldg(bias + nbase + c);
    }
    __syncthreads();
}

// ---------------- the persistent decoder kernel ----------------
__global__ void __launch_bounds__(NTHREADS, 1) dec_kernel(
    const float* __restrict__ z,     const float* __restrict__ lin1_w, const float* __restrict__ lin1_b,
    const float* __restrict__ ln1_w, const float* __restrict__ ln1_b,
    const float* __restrict__ w_ih0, const float* __restrict__ w_hh0,  const float* __restrict__ b0,
    const float* __restrict__ w_ih1, const float* __restrict__ w_hh1,  const float* __restrict__ b1,
    const float* __restrict__ p1_w,  const float* __restrict__ p1_b,
    const float* __restrict__ pln_w, const float* __restrict__ pln_b,
    const float* __restrict__ p2_w,  const float* __restrict__ p2_b,
    float* __restrict__ out)
{
    extern __shared__ char pool[];
    __shared__ float redA[8], redB[8];
    const int bid = blockIdx.x, nb = gridDim.x, tid = threadIdx.x;
    const int lane = tid & 31;
    const int grp = bid >> 5, slot = bid & 31;
    uint32_t raw = smem_u32(pool);
    uint32_t pbase = (raw + 1023) & ~1023u;
    char* P = pool + (pbase - raw);
    unsigned epoch = g_release;
    unsigned gep = g_flag[grp][slot];
    Pipe pp;
    #pragma unroll
    for (int s = 0; s < NSTAGE; s++) { pp.fullph[s] = 0; pp.emptyph[s] = 0; }
    pp.pcnt = 0; pp.ccnt = 0;

    if (tid == 0) {
        #pragma unroll
        for (int s = 0; s < NSTAGE; s++) {
            MBAR_INIT(pbase + (s << 3), 1);       // full: tx-based
            MBAR_INIT(pbase + 64 + (s << 3), 8);  // empty: one arrive per warp
        }
    }
    __syncthreads();
    if (lane == 0) {
        #pragma unroll
        for (int s = 0; s < NSTAGE; s++) MBAR_ARRIVE(pbase + 64 + (s << 3));
    }
    __syncthreads();

    // ---- S0: pack weights (fp16, 128-chunks); pack z; transpose p2; zero x
    {
        int gt = bid * NTHREADS + tid, gs = nb * NTHREADS;
        pack_w(lin1_w, g_lin1p, LATENT, 64, 32, 0, gt, gs);
        pack_w(w_ih0,  g_wih0p, NOUT, 128, 32, 1, gt, gs);
        pack_w(w_hh0,  g_whh0p, HID, 128, 32, 1, gt, gs);
        pack_w(w_ih1,  g_wih1p, HID, 128, 32, 1, gt, gs);
        pack_w(w_hh1,  g_whh1p, HID, 128, 32, 1, gt, gs);
        pack_w(p1_w,   g_p1p,   HID, 32, 32, 0, gt, gs);
        // z: 2 chunks x 4 mg x 128 rows x 32 k4
        for (int i = gt; i < 2 * 4 * 128 * 32; i += gs) {
            int k4 = i & 31, r = (i >> 5) & 127, mg = (i >> 12) & 3, c = i >> 14;
            float4 v = *(const float4*)(z + (size_t)(mg * 128 + r) * LATENT + c * 128 + k4 * 4);
            fp16 h[4];
            h[0] = __float2half_rn(v.x); h[1] = __float2half_rn(v.y);
            h[2] = __float2half_rn(v.z); h[3] = __float2half_rn(v.w);
            size_t d = (size_t)(c * 4 + mg) * ABLK + (size_t)r * LDA + k4 * 4;
            *(uint2*)(g_zp + d) = *(uint2*)h;
        }
        for (int i = gt; i < 256 * 128; i += gs) {
            int o = i & 127, kq = i >> 7;
            g_p2q[i] = *(const float4*)(p2_w + (size_t)o * HID + kq * 4);
        }
        for (int i = gt; i < 4 * ABLK; i += gs) {
            g_xp[i] = __float2half_rn(0.f);
        }
    }
    gridbar(epoch);

    // ---- S1: u = z @ lin1_w^T + lin1_b  (512 x 2048): 128 tiles of 128x64
    {
        int mg = grp, nt = slot;
        CFrag acc[2][2];
        #pragma unroll
        for (int i = 0; i < 2; i++) { wmma::fill_fragment(acc[i][0], 0.f); wmma::fill_fragment(acc[i][1], 0.f); }
        Seg sg[1] = {{g_zp + (size_t)mg * ABLK,
                      g_lin1p + (size_t)nt * 2 * (64 * 136),
                      2, 4 * ABLK, 64 * 136}};
        gemm_pk<2>(acc, P, pbase, sg, 1, pp);
        store_epi<2>(acc, P, lin1_b, g_u, 2 * HID, mg << 7, nt << 6);
    }
    garrive(grp, slot, gep); gwait(grp, gep);

    // ---- S2: LayerNorm(2048) + gelu -> h0/c0 (both cells)
    {
        float* pf = (float*)(P + 1024);
        const int g = tid >> 7, lt = tid & 127, w4 = (tid >> 5) & 3;
        {
            int grp2 = bid;
            for (int pass = 0; pass < 2; pass++) {
                int row = (grp2 << 2) + pass * 2 + g;
                const float* urow = g_u + (size_t)row * 2 * HID;
                float ls = 0.f, lq = 0.f;
                #pragma unroll
                for (int u = 0; u < 16; u++) {
                    float v = __ldcg(urow + u * 128 + lt);
                    pf[g * 2048 + u * 128 + lt] = v;
                    ls += v; lq += v * v;
                }
                #pragma unroll
                for (int o = 16; o > 0; o >>= 1) {
                    ls += __shfl_down_sync(0xffffffffu, ls, o);
                    lq += __shfl_down_sync(0xffffffffu, lq, o);
                }
                if (lane == 0) { redA[g * 4 + w4] = ls; redB[g * 4 + w4] = lq; }
                __syncthreads();
                float S = redA[g * 4] + redA[g * 4 + 1] + redA[g * 4 + 2] + redA[g * 4 + 3];
                float Q = redB[g * 4] + redB[g * 4 + 1] + redB[g * 4 + 2] + redB[g * 4 + 3];
                float mu = S * (1.f / 2048.f);
                float rstd = rsqrtf(Q * (1.f / 2048.f) - mu * mu + 1e-5f);
                #pragma unroll
                for (int u = 0; u < 16; u++) {
                    int i = u * 128 + lt;
                    float v = (pf[g * 2048 + i] - mu) * rstd * __ldg(ln1_w + i) + __ldg(ln1_b + i);
                    float ge = v * normcdff(v);
                    if (i < HID) {
                        fp16 hv = __float2half_rn(ge);
                        size_t off = pk_off(row, i);
                        g_h1p[0][off] = hv;
                        g_h2p[0][off] = hv;
                    } else {
                        g_c1[0][(size_t)row * HID + i - HID] = ge;
                        g_c2[0][(size_t)row * HID + i - HID] = ge;
                    }
                }
                __syncthreads();
            }
        }
    }
    garrive(grp, slot, gep); gwait(grp, gep);

    // ---- main sequential loop
    // P1's big seg_h (h1 @ w_hh0, 8 chunks) for step s is computed during step s-1
    // (split around P3/P4 waits to hide them). Accumulation order preserved:
    // chunks 0-3, 4-7, then seg_x — identical arithmetic to the unsplit version.
    const int mg = grp, ntl = slot;
    CFrag accP1[2][4];
    #pragma unroll
    for (int i = 0; i < 2; i++)
        #pragma unroll
        for (int j = 0; j < 4; j++) wmma::fill_fragment(accP1[i][j], 0.f);
    {   // seed seg_h for s=0 (h1[0] from S2, synced by S2 barrier)
        Seg sgh[1] = {{g_h1p[0] + (size_t)mg * ABLK,
                       g_whh0p + (size_t)ntl * 8 * (128 * 136),
                       8, 4 * ABLK, 128 * 136}};
        gemm_pk<4>(accP1, P, pbase, sgh, 1, pp);
    }

    for (int s = 0; s < SEQL; s++) {
        const int pi = s & 1, po = pi ^ 1;

        // P1 completion: wait x -> seg_x (1 chunk) -> epilogue -> arrive
        {
            gwait(grp, gep);                    // x from P4(s-1) ready (no-op at s=0)
            Seg sgx[1] = {{g_xp + (size_t)mg * ABLK,
                           g_wih0p + (size_t)ntl * 1 * (128 * 136),
                           1, 4 * ABLK, 128 * 136}};
            gemm_pk<4>(accP1, P, pbase, sgx, 1, pp);
            lstm_epi(accP1, P, b0, g_c1[pi], g_c1[po], g_h1p[po], mg << 7, ntl << 5);
        }
        garrive(grp, slot, gep);

        // P2: seg_h2 (8 chunks, no dep on P1) -> wait h1 -> seg_h1 (8 chunks) -> epilogue -> arrive
        {
            CFrag acc[2][4];
            #pragma unroll
            for (int i = 0; i < 2; i++)
                #pragma unroll
                for (int j = 0; j < 4; j++) wmma::fill_fragment(acc[i][j], 0.f);
            Seg sg2[1] = {{g_h2p[pi] + (size_t)mg * ABLK,
                           g_whh1p + (size_t)ntl * 8 * (128 * 136),
                           8, 4 * ABLK, 128 * 136}};
            gemm_pk<4>(acc, P, pbase, sg2, 1, pp);
            gwait(grp, gep);                    // h1_new ready
            Seg sg1[1] = {{g_h1p[po] + (size_t)mg * ABLK,
                           g_wih1p + (size_t)ntl * 8 * (128 * 136),
                           8, 4 * ABLK, 128 * 136}};
            gemm_pk<4>(acc, P, pbase, sg1, 1, pp);
            lstm_epi(acc, P, b1, g_c2[pi], g_c2[po], g_h2p[po], mg << 7, ntl << 5);
        }
        garrive(grp, slot, gep);

        const bool hoist = (s + 1 < SEQL);
        if (hoist) {   // reseed accP1; seg_h(s+1) part A (chunks 0-3) hides P3's wait
            #pragma unroll
            for (int i = 0; i < 2; i++)
                #pragma unroll
                for (int j = 0; j < 4; j++) wmma::fill_fragment(accP1[i][j], 0.f);
            Seg sa[1] = {{g_h1p[po] + (size_t)mg * ABLK,
                          g_whh0p + (size_t)ntl * 8 * (128 * 136),
                          4, 4 * ABLK, 128 * 136}};
            gemm_pk<4>(accP1, P, pbase, sa, 1, pp);
        }

        // P3: wait h2 -> t = h2_new @ p1_w^T + p1_b (8 chunks) -> arrive
        gwait(grp, gep);
        {
            CFrag acc[2][1];
            wmma::fill_fragment(acc[0][0], 0.f);
            wmma::fill_fragment(acc[1][0], 0.f);
            Seg sg[1] = {{g_h2p[po] + (size_t)mg * ABLK,
                          g_p1p + (size_t)ntl * 8 * (32 * 136),
                          8, 4 * ABLK, 32 * 136}};
            gemm_pk<1>(acc, P, pbase, sg, 1, pp);
            store_epi<1>(acc, P, p1_b, g_t, HID, mg << 7, ntl << 5);
        }
        garrive(grp, slot, gep);

        if (hoist) {   // seg_h(s+1) part B (chunks 4-7) hides P4's wait
            Seg sb[1] = {{g_h1p[po] + (size_t)mg * ABLK + 4 * (size_t)(4 * ABLK),
                          g_whh0p + (size_t)ntl * 8 * (128 * 136) + 4 * (size_t)(128 * 136),
                          4, 4 * ABLK, 128 * 136}};
            gemm_pk<4>(accP1, P, pbase, sb, 1, pp);
        }

        // P4: wait t -> LayerNorm + gelu + GEMV -> x, out -> arrive
        gwait(grp, gep);
        {
            float* pf = (float*)(P + 1024);
            float* psum = pf + 4096;
            const int g = tid >> 7, lt = tid & 127, w4 = (tid >> 5) & 3;
            const int grp2 = bid;
            for (int pass = 0; pass < 2; pass++) {
                int rr = pass * 2 + g;
                int row = (grp2 << 2) + rr;
                const float* trow = g_t + (size_t)row * HID;
                float vb[8]; float ls = 0.f, lq = 0.f;
                #pragma unroll
                for (int u = 0; u < 8; u++) {
                    float v = __ldcg(trow + u * 128 + lt);
                    vb[u] = v; ls += v; lq += v * v;
                }
                #pragma unroll
                for (int o = 16; o > 0; o >>= 1) {
                    ls += __shfl_down_sync(0xffffffffu, ls, o);
                    lq += __shfl_down_sync(0xffffffffu, lq, o);
                }
                if (lane == 0) { redA[g * 4 + w4] = ls; redB[g * 4 + w4] = lq; }
                __syncthreads();
                float S = redA[g * 4] + redA[g * 4 + 1] + redA[g * 4 + 2] + redA[g * 4 + 3];
                float Q = redB[g * 4] + redB[g * 4 + 1] + redB[g * 4 + 2] + redB[g * 4 + 3];
                float mu = S * (1.f / 1024.f);
                float rstd = rsqrtf(Q * (1.f / 1024.f) - mu * mu + 1e-5f);
                #pragma unroll
                for (int u = 0; u < 8; u++) {
                    int i = u * 128 + lt;
                    float v = (vb[u] - mu) * rstd * __ldg(pln_w + i) + __ldg(pln_b + i);
                    pf[rr * 1024 + i] = v * normcdff(v);
                }
                __syncthreads();
            }
            {
                float a0 = 0.f, a1 = 0.f, a2 = 0.f, a3 = 0.f;
                const int kq0 = g * 128;
                #pragma unroll 2
                for (int kq = 0; kq < 128; kq++) {
                    float4 wv = g_p2q[(size_t)(kq0 + kq) * 128 + lt];
                    float4 g0 = *(const float4*)(pf + 0 * 1024 + (kq0 + kq) * 4);
                    float4 g1 = *(const float4*)(pf + 1 * 1024 + (kq0 + kq) * 4);
                    float4 g2 = *(const float4*)(pf + 2 * 1024 + (kq0 + kq) * 4);
                    float4 g3 = *(const float4*)(pf + 3 * 1024 + (kq0 + kq) * 4);
                    a0 += g0.x * wv.x + g0.y * wv.y + g0.z * wv.z + g0.w * wv.w;
                    a1 += g1.x * wv.x + g1.y * wv.y + g1.z * wv.z + g1.w * wv.w;
                    a2 += g2.x * wv.x + g2.y * wv.y + g2.z * wv.z + g2.w * wv.w;
                    a3 += g3.x * wv.x + g3.y * wv.y + g3.z * wv.z + g3.w * wv.w;
                }
                psum[(0 * 2 + g) * 128 + lt] = a0;
                psum[(1 * 2 + g) * 128 + lt] = a1;
                psum[(2 * 2 + g) * 128 + lt] = a2;
                psum[(3 * 2 + g) * 128 + lt] = a3;
            }
            __syncthreads();
            for (int idx = tid; idx < 512; idx += NTHREADS) {
                int r = idx >> 7, o = idx & 127;
                int row = (grp2 << 2) + r;
                float y = psum[(r * 2) * 128 + o] + psum[(r * 2 + 1) * 128 + o] + __ldg(p2_b + o);
                g_xp[pk_off(row, o)] = __float2half_rn(y);
                out[(size_t)row * SEQL * NOUT + s * NOUT + o] = y;
            }
            __syncthreads();
        }
        garrive(grp, slot, gep);
    }
}

// ---------------- launch ----------------
extern "C" void kernel_launch(void* const* d_in, const int* in_sizes, int n_in,
                              void* d_out, int out_size) {
    (void)in_sizes; (void)n_in; (void)out_size;
    cudaFuncSetAttribute(dec_kernel, cudaFuncAttributeMaxDynamicSharedMemorySize, SMEM_BYTES);

    const float* z      = (const float*)d_in[0];
    const float* lin1_w = (const float*)d_in[1];
    const float* lin1_b = (const float*)d_in[2];
    const float* ln1_w  = (const float*)d_in[3];
    const float* ln1_b  = (const float*)d_in[4];
    const float* w_ih0  = (const float*)d_in[5];
    const float* w_hh0  = (const float*)d_in[6];
    const float* b0     = (const float*)d_in[7];
    const float* w_ih1  = (const float*)d_in[8];
    const float* w_hh1  = (const float*)d_in[9];
    const float* b1     = (const float*)d_in[10];
    const float* p1_w   = (const float*)d_in[11];
    const float* p1_b   = (const float*)d_in[12];
    const float* pln_w  = (const float*)d_in[13];
    const float* pln_b  = (const float*)d_in[14];
    const float* p2_w   = (const float*)d_in[15];
    const float* p2_b   = (const float*)d_in[16];

    dec_kernel<<<NBLOCKS, NTHREADS, SMEM_BYTES>>>(
        z, lin1_w, lin1_b, ln1_w, ln1_b,
        w_ih0, w_hh0, b0, w_ih1, w_hh1, b1,
        p1_w, p1_b, pln_w, pln_b, p2_w, p2_b,
        (float*)d_out);
}